// round 3
// baseline (speedup 1.0000x reference)
#include <cuda_runtime.h>
#include <cuda_bf16.h>
#include <math.h>

#define N_CELLS_MAX (1 << 20)

// ---------------- global scratch (static allocation: allowed) ----------------
__device__ int g_list[3][N_CELLS_MAX];
__device__ int g_cnt[3];

// ---------------- helpers ----------------
__device__ __forceinline__ unsigned long long fma2(unsigned long long a,
                                                   unsigned long long b,
                                                   unsigned long long c) {
    unsigned long long d;
    asm("fma.rn.f32x2 %0, %1, %2, %3;" : "=l"(d) : "l"(a), "l"(b), "l"(c));
    return d;
}
__device__ __forceinline__ unsigned long long pack2(float a, float b) {
    unsigned long long r;
    asm("mov.b64 %0, {%1, %2};" : "=l"(r) : "f"(a), "f"(b));
    return r;
}
__device__ __forceinline__ void unpack2(unsigned long long v, float& a, float& b) {
    asm("mov.b64 {%0, %1}, %2;" : "=f"(a), "=f"(b) : "l"(v));
}

// tanh(x) = sign(x) * (1 - e) / (1 + e), e = exp(-2|x|)
__device__ __forceinline__ float tanh_fast(float x) {
    float ax = fabsf(x);
    float e;
    asm("ex2.approx.f32 %0, %1;" : "=f"(e) : "f"(ax * -2.8853900817779268f));
    float r = __fdividef(1.0f - e, 1.0f + e);
    return copysignf(r, x);
}

// ---------------- K0: zero counters ----------------
__global__ void zero_kernel() {
    if (threadIdx.x < 3) g_cnt[threadIdx.x] = 0;
}

// ---------------- Phase A: classify + contact/vacuum fast path ----------------
#define TA 256
__global__ void __launch_bounds__(TA)
phaseA(const float* __restrict__ P, const float* __restrict__ U,
       const float* __restrict__ F,
       const float* __restrict__ cmax, const float* __restrict__ cmin,
       float* __restrict__ out, int N)
{
    int n = blockIdx.x * TA + threadIdx.x;
    if (n >= N) return;

    const float2* P2 = reinterpret_cast<const float2*>(P + (size_t)n * 6);
    float2 p0 = P2[0], p1 = P2[1], p2 = P2[2];

    bool flip = p1.y > p1.x;
    if (flip) {
        float t;
        t = p0.x; p0.x = p0.y;  p0.y = t;
        t = p1.x; p1.x = p1.y;  p1.y = t;
        t = p2.x; p2.x = -p2.y; p2.y = -t;
    }

    float d0 = fabsf(p0.y - p0.x), d1 = fabsf(p1.y - p1.x), d2 = fabsf(p2.y - p2.x);
    bool cont = fmaxf(d0, fmaxf(d1, d2)) < 0.005f;

    // classify (gamma = 5/3)
    const float G = 5.0f / 3.0f;
    float c0 = sqrtf(G * p1.x / p0.x);
    float c1 = sqrtf(G * p1.y / p0.y);
    float dv = p2.y - p2.x;
    float num = (c0 + c1) - (1.0f / 3.0f) * dv;
    float den = c0 * __powf(p1.x, -0.2f) + c1 * __powf(p1.y, -0.2f);
    float ps = fmaxf(num / den, 1e-8f);
    float ps2 = ps * ps;
    float p_star = ps2 * ps2 * ps;
    bool vac = dv >= 3.0f * (c0 + c1);
    bool dsb = p_star > fmaxf(p1.x, p1.y);
    bool drb = p_star < fminf(p1.x, p1.y);
    int label = vac ? 3 : (drb ? 1 : (dsb ? 0 : 2));

    bool want = !cont && (label < 3);

    if (cont) {
        // HLLE path: need U, F, cmax, cmin
        const float2* U2 = reinterpret_cast<const float2*>(U + (size_t)n * 6);
        const float2* F2 = reinterpret_cast<const float2*>(F + (size_t)n * 6);
        float2 u0 = U2[0], u1 = U2[1], u2 = U2[2];
        float2 f0 = F2[0], f1 = F2[1], f2 = F2[2];
        float cm = cmax[n], cn = cmin[n];
        if (flip) {
            float t;
            t = u0.x; u0.x = u0.y;  u0.y = t;
            t = u1.x; u1.x = u1.y;  u1.y = t;
            t = u2.x; u2.x = -u2.y; u2.y = -t;
            t = f0.x; f0.x = -f0.y; f0.y = -t;
            t = f1.x; f1.x = -f1.y; f1.y = -t;
            t = f2.x; f2.x = f2.y;  f2.y = t;
        }
        float inv = 1.0f / (cm - cn);
        float cmcn = cm * cn;
        float h0 = (cm * f0.x - cn * f0.y + cmcn * (u0.y - u0.x)) * inv;
        float h1 = (cm * f1.x - cn * f1.y + cmcn * (u1.y - u1.x)) * inv;
        float h2 = (cm * f2.x - cn * f2.y + cmcn * (u2.y - u2.x)) * inv;
        if (flip) { h0 = -h0; h1 = -h1; }
        out[(size_t)n * 3 + 0] = h0;
        out[(size_t)n * 3 + 1] = h1;
        out[(size_t)n * 3 + 2] = h2;
    } else if (label == 3) {
        out[(size_t)n * 3 + 0] = 0.0f;
        out[(size_t)n * 3 + 1] = 0.0f;
        out[(size_t)n * 3 + 2] = 0.0f;
    }

    // warp-aggregated list push
    unsigned lane = threadIdx.x & 31;
    unsigned lt_mask = (1u << lane) - 1u;
    int tag = n | (flip ? (int)0x80000000 : 0);
    #pragma unroll
    for (int l = 0; l < 3; l++) {
        unsigned m = __ballot_sync(0xffffffffu, want && label == l);
        if (m) {
            int leader = __ffs(m) - 1;
            int base = 0;
            if ((int)lane == leader) base = atomicAdd(&g_cnt[l], __popc(m));
            base = __shfl_sync(0xffffffffu, base, leader);
            if (want && label == l)
                g_list[l][base + __popc(m & lt_mask)] = tag;
        }
    }
}

// ---------------- Phase B: label-uniform MLP, 4 cells/thread ----------------
#define TB 128
#define CPT 4
#define CPB (TB * CPT)  // 512
#define GRID_B 1184

__global__ void __launch_bounds__(TB, 2)
phaseB(const float* __restrict__ P, const float* __restrict__ U,
       const float* __restrict__ F,
       const float* __restrict__ cmax, const float* __restrict__ cmin,
       const float* __restrict__ W1_ds, const float* __restrict__ b1_ds,
       const float* __restrict__ W2_ds, const float* __restrict__ b2_ds,
       const float* __restrict__ W1_dr, const float* __restrict__ b1_dr,
       const float* __restrict__ W2_dr, const float* __restrict__ b2_dr,
       const float* __restrict__ W1_rs, const float* __restrict__ b1_rs,
       const float* __restrict__ W2_rs, const float* __restrict__ b2_rs,
       float* __restrict__ out)
{
    __shared__ __align__(16) float w1s[3][1280];
    __shared__ __align__(16) float b1s[3][64];
    __shared__ __align__(16) float w2s[3][192];   // transposed [j][h]
    __shared__ float b2s[3][4];

    {
        const float* w1p[3] = {W1_ds, W1_dr, W1_rs};
        const float* b1p[3] = {b1_ds, b1_dr, b1_rs};
        const float* w2p[3] = {W2_ds, W2_dr, W2_rs};
        const float* b2p[3] = {b2_ds, b2_dr, b2_rs};
        #pragma unroll
        for (int m = 0; m < 3; m++) {
            for (int i = threadIdx.x; i < 1280; i += TB) w1s[m][i] = w1p[m][i];
            for (int i = threadIdx.x; i < 64; i += TB)   b1s[m][i] = b1p[m][i];
            for (int i = threadIdx.x; i < 192; i += TB) {
                int h = i / 3, j = i % 3;
                w2s[m][j * 64 + h] = w2p[m][i];
            }
            if (threadIdx.x < 3) b2s[m][threadIdx.x] = b2p[m][threadIdx.x];
        }
    }
    __syncthreads();

    for (int l = 0; l < 3; l++) {
        int cnt = g_cnt[l];
        for (int base = blockIdx.x * CPB; base < cnt; base += GRID_B * CPB) {
            int pos = base + threadIdx.x * CPT;

            int tags[CPT];
            bool act[CPT];
            #pragma unroll
            for (int c = 0; c < CPT; c++) {
                act[c] = (pos + c) < cnt;
                tags[c] = act[c] ? g_list[l][pos + c] : 0;
            }

            float ft[CPT][20];
            #pragma unroll
            for (int c = 0; c < CPT; c++) {
                int cell = tags[c] & 0x7FFFFFFF;
                bool fl = tags[c] < 0;
                const float2* P2 = reinterpret_cast<const float2*>(P + (size_t)cell * 6);
                const float2* U2 = reinterpret_cast<const float2*>(U + (size_t)cell * 6);
                const float2* F2 = reinterpret_cast<const float2*>(F + (size_t)cell * 6);
                float2 p0 = P2[0], p1 = P2[1], p2 = P2[2];
                float2 u0 = U2[0], u1 = U2[1], u2 = U2[2];
                float2 f0 = F2[0], f1 = F2[1], f2 = F2[2];
                float cm = cmax[cell], cn = cmin[cell];
                if (fl) {
                    float t;
                    t = p0.x; p0.x = p0.y;  p0.y = t;
                    t = p1.x; p1.x = p1.y;  p1.y = t;
                    t = p2.x; p2.x = -p2.y; p2.y = -t;
                    t = u0.x; u0.x = u0.y;  u0.y = t;
                    t = u1.x; u1.x = u1.y;  u1.y = t;
                    t = u2.x; u2.x = -u2.y; u2.y = -t;
                    t = f0.x; f0.x = -f0.y; f0.y = -t;
                    t = f1.x; f1.x = -f1.y; f1.y = -t;
                    t = f2.x; f2.x = f2.y;  f2.y = t;
                }
                ft[c][0] = p0.x;  ft[c][1] = p0.y;
                ft[c][2] = p1.x;  ft[c][3] = p1.y;
                ft[c][4] = p2.x;  ft[c][5] = p2.y;
                ft[c][6] = u0.x;  ft[c][7] = u0.y;
                ft[c][8] = u1.x;  ft[c][9] = u1.y;
                ft[c][10] = u2.x; ft[c][11] = u2.y;
                ft[c][12] = f0.x; ft[c][13] = f0.y;
                ft[c][14] = f1.x; ft[c][15] = f1.y;
                ft[c][16] = f2.x; ft[c][17] = f2.y;
                ft[c][18] = cm;   ft[c][19] = cn;
            }

            unsigned long long oj[CPT][3];
            #pragma unroll
            for (int c = 0; c < CPT; c++)
                #pragma unroll
                for (int j = 0; j < 3; j++) oj[c][j] = 0ull;

            #pragma unroll
            for (int chunk = 0; chunk < 8; chunk++) {
                // init hidden accumulators with b1 chunk (8 units = 4 f32x2)
                const unsigned long long* b1v =
                    reinterpret_cast<const unsigned long long*>(&b1s[l][chunk * 8]);
                unsigned long long ha[CPT][4];
                unsigned long long bb0 = b1v[0], bb1 = b1v[1], bb2 = b1v[2], bb3 = b1v[3];
                #pragma unroll
                for (int c = 0; c < CPT; c++) {
                    ha[c][0] = bb0; ha[c][1] = bb1; ha[c][2] = bb2; ha[c][3] = bb3;
                }

                #pragma unroll
                for (int k = 0; k < 20; k++) {
                    const ulonglong2* wrow =
                        reinterpret_cast<const ulonglong2*>(&w1s[l][k * 64 + chunk * 8]);
                    ulonglong2 wa = wrow[0], wb = wrow[1];
                    #pragma unroll
                    for (int c = 0; c < CPT; c++) {
                        unsigned long long x2 = pack2(ft[c][k], ft[c][k]);
                        ha[c][0] = fma2(x2, wa.x, ha[c][0]);
                        ha[c][1] = fma2(x2, wa.y, ha[c][1]);
                        ha[c][2] = fma2(x2, wb.x, ha[c][2]);
                        ha[c][3] = fma2(x2, wb.y, ha[c][3]);
                    }
                }

                // tanh in place
                #pragma unroll
                for (int c = 0; c < CPT; c++) {
                    #pragma unroll
                    for (int i = 0; i < 4; i++) {
                        float a, b;
                        unpack2(ha[c][i], a, b);
                        ha[c][i] = pack2(tanh_fast(a), tanh_fast(b));
                    }
                }

                // layer 2 partial dot for this chunk
                #pragma unroll
                for (int j = 0; j < 3; j++) {
                    const ulonglong2* w2row =
                        reinterpret_cast<const ulonglong2*>(&w2s[l][j * 64 + chunk * 8]);
                    ulonglong2 wa = w2row[0], wb = w2row[1];
                    #pragma unroll
                    for (int c = 0; c < CPT; c++) {
                        oj[c][j] = fma2(ha[c][0], wa.x, oj[c][j]);
                        oj[c][j] = fma2(ha[c][1], wa.y, oj[c][j]);
                        oj[c][j] = fma2(ha[c][2], wb.x, oj[c][j]);
                        oj[c][j] = fma2(ha[c][3], wb.y, oj[c][j]);
                    }
                }
            }

            #pragma unroll
            for (int c = 0; c < CPT; c++) {
                if (!act[c]) continue;
                int cell = tags[c] & 0x7FFFFFFF;
                bool fl = tags[c] < 0;
                float o[3];
                #pragma unroll
                for (int j = 0; j < 3; j++) {
                    float a, b;
                    unpack2(oj[c][j], a, b);
                    o[j] = (a + b) + b2s[l][j];
                }
                if (fl) { o[0] = -o[0]; o[1] = -o[1]; }
                out[(size_t)cell * 3 + 0] = o[0];
                out[(size_t)cell * 3 + 1] = o[1];
                out[(size_t)cell * 3 + 2] = o[2];
            }
        }
    }
}

// ---------------- launch ----------------
extern "C" void kernel_launch(void* const* d_in, const int* in_sizes, int n_in,
                              void* d_out, int out_size) {
    const float* P     = (const float*)d_in[0];
    const float* U     = (const float*)d_in[1];
    const float* F     = (const float*)d_in[2];
    const float* cmax  = (const float*)d_in[3];
    const float* cmin  = (const float*)d_in[4];
    const float* W1_ds = (const float*)d_in[5];
    const float* b1_ds = (const float*)d_in[6];
    const float* W2_ds = (const float*)d_in[7];
    const float* b2_ds = (const float*)d_in[8];
    const float* W1_dr = (const float*)d_in[9];
    const float* b1_dr = (const float*)d_in[10];
    const float* W2_dr = (const float*)d_in[11];
    const float* b2_dr = (const float*)d_in[12];
    const float* W1_rs = (const float*)d_in[13];
    const float* b1_rs = (const float*)d_in[14];
    const float* W2_rs = (const float*)d_in[15];
    const float* b2_rs = (const float*)d_in[16];

    int N = in_sizes[3];
    float* out = (float*)d_out;

    zero_kernel<<<1, 32>>>();
    phaseA<<<(N + TA - 1) / TA, TA>>>(P, U, F, cmax, cmin, out, N);
    phaseB<<<GRID_B, TB>>>(P, U, F, cmax, cmin,
                           W1_ds, b1_ds, W2_ds, b2_ds,
                           W1_dr, b1_dr, W2_dr, b2_dr,
                           W1_rs, b1_rs, W2_rs, b2_rs,
                           out);
}

// round 4
// speedup vs baseline: 1.3359x; 1.3359x over previous
#include <cuda_runtime.h>
#include <math.h>

#define NMAX (1 << 20)

// ---------------- global scratch ----------------
__device__ float g_feat[3][NMAX][20];
__device__ int   g_tag[3][NMAX];
__device__ int   g_cnt[3];

// ---------------- helpers ----------------
__device__ __forceinline__ unsigned long long fma2(unsigned long long a,
                                                   unsigned long long b,
                                                   unsigned long long c) {
    unsigned long long d;
    asm("fma.rn.f32x2 %0, %1, %2, %3;" : "=l"(d) : "l"(a), "l"(b), "l"(c));
    return d;
}
__device__ __forceinline__ unsigned long long pack2(float a, float b) {
    unsigned long long r;
    asm("mov.b64 %0, {%1, %2};" : "=l"(r) : "f"(a), "f"(b));
    return r;
}
__device__ __forceinline__ void unpack2(unsigned long long v, float& a, float& b) {
    asm("mov.b64 {%0, %1}, %2;" : "=f"(a), "=f"(b) : "l"(v));
}

// tanh(x) = 1 - 2/(1 + e^{2x}); handles +/-inf gracefully, 2 MUFU + 3 FMA-pipe ops
__device__ __forceinline__ float tanh_fast(float x) {
    float e;
    asm("ex2.approx.f32 %0, %1;" : "=f"(e) : "f"(x * 2.8853900817779268f));
    float r;
    asm("rcp.approx.f32 %0, %1;" : "=f"(r) : "f"(e + 1.0f));
    return fmaf(-2.0f, r, 1.0f);
}

// ---------------- Phase A ----------------
#define TA 256
__global__ void __launch_bounds__(TA)
phaseA(const float* __restrict__ P, const float* __restrict__ U,
       const float* __restrict__ F,
       const float* __restrict__ cmax, const float* __restrict__ cmin,
       float* __restrict__ out, int N)
{
    __shared__ int s_cnt[3][TA / 32];
    __shared__ int s_base[3][TA / 32];

    int n = blockIdx.x * TA + threadIdx.x;
    bool valid = n < N;
    int ncl = valid ? n : 0;

    const float2* P2 = reinterpret_cast<const float2*>(P + (size_t)ncl * 6);
    const float2* U2 = reinterpret_cast<const float2*>(U + (size_t)ncl * 6);
    const float2* F2 = reinterpret_cast<const float2*>(F + (size_t)ncl * 6);
    float2 p0 = P2[0], p1 = P2[1], p2 = P2[2];
    float2 u0 = U2[0], u1 = U2[1], u2 = U2[2];
    float2 f0 = F2[0], f1 = F2[1], f2 = F2[2];
    float cm = cmax[ncl], cn = cmin[ncl];

    bool flip = p1.y > p1.x;
    if (flip) {
        float t;
        t = p0.x; p0.x = p0.y;  p0.y = t;
        t = p1.x; p1.x = p1.y;  p1.y = t;
        t = p2.x; p2.x = -p2.y; p2.y = -t;
        t = u0.x; u0.x = u0.y;  u0.y = t;
        t = u1.x; u1.x = u1.y;  u1.y = t;
        t = u2.x; u2.x = -u2.y; u2.y = -t;
        t = f0.x; f0.x = -f0.y; f0.y = -t;
        t = f1.x; f1.x = -f1.y; f1.y = -t;
        t = f2.x; f2.x = f2.y;  f2.y = t;
    }

    float d0 = fabsf(p0.y - p0.x), d1 = fabsf(p1.y - p1.x), d2 = fabsf(p2.y - p2.x);
    bool cont = fmaxf(d0, fmaxf(d1, d2)) < 0.005f;

    const float G = 5.0f / 3.0f;
    float c0 = sqrtf(G * p1.x / p0.x);
    float c1 = sqrtf(G * p1.y / p0.y);
    float dv = p2.y - p2.x;
    float num = (c0 + c1) - (1.0f / 3.0f) * dv;
    float den = c0 * __powf(p1.x, -0.2f) + c1 * __powf(p1.y, -0.2f);
    float ps = fmaxf(num / den, 1e-8f);
    float ps2 = ps * ps;
    float p_star = ps2 * ps2 * ps;
    bool vac = dv >= 3.0f * (c0 + c1);
    bool dsb = p_star > fmaxf(p1.x, p1.y);
    bool drb = p_star < fminf(p1.x, p1.y);
    int label = vac ? 3 : (drb ? 1 : (dsb ? 0 : 2));

    bool want = valid && !cont && (label < 3);

    if (valid && !want) {
        if (cont) {
            float inv = 1.0f / (cm - cn);
            float cmcn = cm * cn;
            float h0 = (cm * f0.x - cn * f0.y + cmcn * (u0.y - u0.x)) * inv;
            float h1 = (cm * f1.x - cn * f1.y + cmcn * (u1.y - u1.x)) * inv;
            float h2 = (cm * f2.x - cn * f2.y + cmcn * (u2.y - u2.x)) * inv;
            if (flip) { h0 = -h0; h1 = -h1; }
            out[(size_t)n * 3 + 0] = h0;
            out[(size_t)n * 3 + 1] = h1;
            out[(size_t)n * 3 + 2] = h2;
        } else {
            out[(size_t)n * 3 + 0] = 0.0f;
            out[(size_t)n * 3 + 1] = 0.0f;
            out[(size_t)n * 3 + 2] = 0.0f;
        }
    }

    // ---- two-level compaction: warp ballot -> block prefix -> one atomic/label ----
    int w = threadIdx.x >> 5;
    unsigned lane = threadIdx.x & 31;
    unsigned lt_mask = (1u << lane) - 1u;
    unsigned m[3];
    #pragma unroll
    for (int l = 0; l < 3; l++) {
        m[l] = __ballot_sync(0xffffffffu, want && label == l);
        if (lane == 0) s_cnt[l][w] = __popc(m[l]);
    }
    __syncthreads();
    if (threadIdx.x < 3) {
        int l = threadIdx.x;
        int tot = 0;
        #pragma unroll
        for (int i = 0; i < TA / 32; i++) tot += s_cnt[l][i];
        int base = tot ? atomicAdd(&g_cnt[l], tot) : 0;
        #pragma unroll
        for (int i = 0; i < TA / 32; i++) {
            s_base[l][i] = base;
            base += s_cnt[l][i];
        }
    }
    __syncthreads();

    if (want) {
        int pos = s_base[label][w] + __popc(m[label] & lt_mask);
        float4* dst = reinterpret_cast<float4*>(g_feat[label][pos]);
        dst[0] = make_float4(p0.x, p0.y, p1.x, p1.y);
        dst[1] = make_float4(p2.x, p2.y, u0.x, u0.y);
        dst[2] = make_float4(u1.x, u1.y, u2.x, u2.y);
        dst[3] = make_float4(f0.x, f0.y, f1.x, f1.y);
        dst[4] = make_float4(f2.x, f2.y, cm, cn);
        g_tag[label][pos] = n | (flip ? (int)0x80000000 : 0);
    }
}

// ---------------- Phase B: label-uniform MLP, cells staged in smem ----------------
#define TB   128
#define CPT  8
#define GB   (TB * CPT)   // 1024 cells per tile
#define SFT  21           // smem feature stride (odd -> conflict-free)
#define GRID_B 296

// dynamic smem layout (floats)
#define OFF_FT  0
#define OFF_W1  (GB * SFT)                 // 21504
#define OFF_B1  (OFF_W1 + 3 * 1280)
#define OFF_W2  (OFF_B1 + 3 * 64)
#define OFF_B2  (OFF_W2 + 3 * 192)
#define SMEM_FLOATS (OFF_B2 + 12)
#define SMEM_B_BYTES (SMEM_FLOATS * 4)

__global__ void __launch_bounds__(TB)
phaseB(const float* __restrict__ W1_ds, const float* __restrict__ b1_ds,
       const float* __restrict__ W2_ds, const float* __restrict__ b2_ds,
       const float* __restrict__ W1_dr, const float* __restrict__ b1_dr,
       const float* __restrict__ W2_dr, const float* __restrict__ b2_dr,
       const float* __restrict__ W1_rs, const float* __restrict__ b1_rs,
       const float* __restrict__ W2_rs, const float* __restrict__ b2_rs,
       float* __restrict__ out)
{
    extern __shared__ float sm[];
    float* sft = sm + OFF_FT;
    float* w1s = sm + OFF_W1;
    float* b1s = sm + OFF_B1;
    float* w2s = sm + OFF_W2;
    float* b2s = sm + OFF_B2;

    {
        const float* w1p[3] = {W1_ds, W1_dr, W1_rs};
        const float* b1p[3] = {b1_ds, b1_dr, b1_rs};
        const float* w2p[3] = {W2_ds, W2_dr, W2_rs};
        const float* b2p[3] = {b2_ds, b2_dr, b2_rs};
        #pragma unroll
        for (int mI = 0; mI < 3; mI++) {
            for (int i = threadIdx.x; i < 1280; i += TB) w1s[mI * 1280 + i] = w1p[mI][i];
            for (int i = threadIdx.x; i < 64; i += TB)   b1s[mI * 64 + i] = b1p[mI][i];
            for (int i = threadIdx.x; i < 192; i += TB) {
                int h = i / 3, j = i % 3;
                w2s[mI * 192 + j * 64 + h] = w2p[mI][i];
            }
            if (threadIdx.x < 3) b2s[mI * 4 + threadIdx.x] = b2p[mI][threadIdx.x];
        }
    }

    int c0 = g_cnt[0], c1 = g_cnt[1], c2 = g_cnt[2];
    int t0 = (c0 + GB - 1) / GB, t1 = (c1 + GB - 1) / GB, t2 = (c2 + GB - 1) / GB;
    int T = t0 + t1 + t2;

    int lane = threadIdx.x & 31;
    int w = threadIdx.x >> 5;

    for (int t = blockIdx.x; t < T; t += GRID_B) {
        int l, ti, cnt;
        if (t < t0)           { l = 0; ti = t;           cnt = c0; }
        else if (t < t0 + t1) { l = 1; ti = t - t0;      cnt = c1; }
        else                  { l = 2; ti = t - t0 - t1; cnt = c2; }
        int base = ti * GB;
        int todo = min(GB, cnt - base);

        __syncthreads();   // previous tile's compute done before restaging
        // stage features: GB records x 20 floats, coalesced float4 loads
        {
            const float4* src = reinterpret_cast<const float4*>(g_feat[l][base]);
            for (int i = threadIdx.x; i < GB * 5; i += TB) {
                int slot = i / 5, q = i - slot * 5;
                float4 v = make_float4(0.f, 0.f, 0.f, 0.f);
                if (slot < todo) v = src[(size_t)slot * 5 + q];
                float* d = &sft[slot * SFT + q * 4];
                d[0] = v.x; d[1] = v.y; d[2] = v.z; d[3] = v.w;
            }
        }
        __syncthreads();

        const float* w1 = w1s + l * 1280;
        const float* w2 = w2s + l * 192;
        const unsigned long long* b1v =
            reinterpret_cast<const unsigned long long*>(b1s + l * 64);

        float oj[CPT][3];
        #pragma unroll
        for (int c = 0; c < CPT; c++) { oj[c][0] = 0.f; oj[c][1] = 0.f; oj[c][2] = 0.f; }

        int slot0 = w * (32 * CPT) + lane;   // this lane's cell c lives at slot0 + 32*c

        for (int chunk = 0; chunk < 8; chunk++) {
            unsigned long long bb0 = b1v[chunk * 4 + 0];
            unsigned long long bb1 = b1v[chunk * 4 + 1];
            unsigned long long bb2 = b1v[chunk * 4 + 2];
            unsigned long long bb3 = b1v[chunk * 4 + 3];
            unsigned long long ha[CPT][4];
            #pragma unroll
            for (int c = 0; c < CPT; c++) {
                ha[c][0] = bb0; ha[c][1] = bb1; ha[c][2] = bb2; ha[c][3] = bb3;
            }

            const float* fcol = sft + slot0 * SFT;
            #pragma unroll 2
            for (int k = 0; k < 20; k++) {
                const ulonglong2* wrow =
                    reinterpret_cast<const ulonglong2*>(w1 + k * 64 + chunk * 8);
                ulonglong2 wa = wrow[0], wb = wrow[1];
                #pragma unroll
                for (int c = 0; c < CPT; c++) {
                    float x = fcol[c * (32 * SFT) + k];
                    unsigned long long x2 = pack2(x, x);
                    ha[c][0] = fma2(x2, wa.x, ha[c][0]);
                    ha[c][1] = fma2(x2, wa.y, ha[c][1]);
                    ha[c][2] = fma2(x2, wb.x, ha[c][2]);
                    ha[c][3] = fma2(x2, wb.y, ha[c][3]);
                }
            }

            #pragma unroll
            for (int c = 0; c < CPT; c++) {
                #pragma unroll
                for (int i = 0; i < 4; i++) {
                    float a, b;
                    unpack2(ha[c][i], a, b);
                    ha[c][i] = pack2(tanh_fast(a), tanh_fast(b));
                }
            }

            #pragma unroll
            for (int j = 0; j < 3; j++) {
                const ulonglong2* w2row =
                    reinterpret_cast<const ulonglong2*>(w2 + j * 64 + chunk * 8);
                ulonglong2 va = w2row[0], vb = w2row[1];
                #pragma unroll
                for (int c = 0; c < CPT; c++) {
                    unsigned long long tacc = fma2(ha[c][0], va.x,
                                             fma2(ha[c][1], va.y,
                                             fma2(ha[c][2], vb.x,
                                             fma2(ha[c][3], vb.y, pack2(0.f, 0.f)))));
                    float a, b;
                    unpack2(tacc, a, b);
                    oj[c][j] += a + b;
                }
            }
        }

        #pragma unroll
        for (int c = 0; c < CPT; c++) {
            int gslot = base + slot0 + 32 * c;
            if (gslot < cnt) {
                int tag = g_tag[l][gslot];
                int cell = tag & 0x7FFFFFFF;
                bool fl = tag < 0;
                float o0 = oj[c][0] + b2s[l * 4 + 0];
                float o1 = oj[c][1] + b2s[l * 4 + 1];
                float o2 = oj[c][2] + b2s[l * 4 + 2];
                if (fl) { o0 = -o0; o1 = -o1; }
                out[(size_t)cell * 3 + 0] = o0;
                out[(size_t)cell * 3 + 1] = o1;
                out[(size_t)cell * 3 + 2] = o2;
            }
        }
    }
}

// ---------------- launch ----------------
extern "C" void kernel_launch(void* const* d_in, const int* in_sizes, int n_in,
                              void* d_out, int out_size) {
    const float* P     = (const float*)d_in[0];
    const float* U     = (const float*)d_in[1];
    const float* F     = (const float*)d_in[2];
    const float* cmax  = (const float*)d_in[3];
    const float* cmin  = (const float*)d_in[4];
    const float* W1_ds = (const float*)d_in[5];
    const float* b1_ds = (const float*)d_in[6];
    const float* W2_ds = (const float*)d_in[7];
    const float* b2_ds = (const float*)d_in[8];
    const float* W1_dr = (const float*)d_in[9];
    const float* b1_dr = (const float*)d_in[10];
    const float* W2_dr = (const float*)d_in[11];
    const float* b2_dr = (const float*)d_in[12];
    const float* W1_rs = (const float*)d_in[13];
    const float* b1_rs = (const float*)d_in[14];
    const float* W2_rs = (const float*)d_in[15];
    const float* b2_rs = (const float*)d_in[16];

    int N = in_sizes[3];
    float* out = (float*)d_out;

    cudaFuncSetAttribute(phaseB, cudaFuncAttributeMaxDynamicSharedMemorySize,
                         SMEM_B_BYTES);

    void* cnt_ptr = nullptr;
    cudaGetSymbolAddress(&cnt_ptr, g_cnt);
    cudaMemsetAsync(cnt_ptr, 0, 3 * sizeof(int));

    phaseA<<<(N + TA - 1) / TA, TA>>>(P, U, F, cmax, cmin, out, N);
    phaseB<<<GRID_B, TB, SMEM_B_BYTES>>>(W1_ds, b1_ds, W2_ds, b2_ds,
                                         W1_dr, b1_dr, W2_dr, b2_dr,
                                         W1_rs, b1_rs, W2_rs, b2_rs,
                                         out);
}

// round 5
// speedup vs baseline: 1.5333x; 1.1477x over previous
#include <cuda_runtime.h>
#include <math.h>

#define NMAX (1 << 20)

// ---------------- global scratch ----------------
__device__ float g_feat[3][NMAX][20];
__device__ int   g_tag[3][NMAX];
__device__ int   g_cnt[3];

// ---------------- helpers ----------------
__device__ __forceinline__ unsigned long long fma2(unsigned long long a,
                                                   unsigned long long b,
                                                   unsigned long long c) {
    unsigned long long d;
    asm("fma.rn.f32x2 %0, %1, %2, %3;" : "=l"(d) : "l"(a), "l"(b), "l"(c));
    return d;
}
__device__ __forceinline__ unsigned long long pack2(float a, float b) {
    unsigned long long r;
    asm("mov.b64 %0, {%1, %2};" : "=l"(r) : "f"(a), "f"(b));
    return r;
}
__device__ __forceinline__ void unpack2(unsigned long long v, float& a, float& b) {
    asm("mov.b64 {%0, %1}, %2;" : "=f"(a), "=f"(b) : "l"(v));
}

// tanh(x) = 1 - 2/(1 + e^{2x}); 2 MUFU + 3 fma-pipe ops
__device__ __forceinline__ float tanh_fast(float x) {
    float e;
    asm("ex2.approx.f32 %0, %1;" : "=f"(e) : "f"(x * 2.8853900817779268f));
    float r;
    asm("rcp.approx.f32 %0, %1;" : "=f"(r) : "f"(e + 1.0f));
    return fmaf(-2.0f, r, 1.0f);
}

// ---------------- Phase A ----------------
#define TA 256
__global__ void __launch_bounds__(TA)
phaseA(const float* __restrict__ P, const float* __restrict__ U,
       const float* __restrict__ F,
       const float* __restrict__ cmax, const float* __restrict__ cmin,
       float* __restrict__ out, int N)
{
    __shared__ int s_cnt[3][TA / 32];
    __shared__ int s_base[3][TA / 32];

    int n = blockIdx.x * TA + threadIdx.x;
    bool valid = n < N;
    int ncl = valid ? n : 0;

    const float2* P2 = reinterpret_cast<const float2*>(P + (size_t)ncl * 6);
    const float2* U2 = reinterpret_cast<const float2*>(U + (size_t)ncl * 6);
    const float2* F2 = reinterpret_cast<const float2*>(F + (size_t)ncl * 6);
    float2 p0 = P2[0], p1 = P2[1], p2 = P2[2];
    float2 u0 = U2[0], u1 = U2[1], u2 = U2[2];
    float2 f0 = F2[0], f1 = F2[1], f2 = F2[2];
    float cm = cmax[ncl], cn = cmin[ncl];

    bool flip = p1.y > p1.x;
    if (flip) {
        float t;
        t = p0.x; p0.x = p0.y;  p0.y = t;
        t = p1.x; p1.x = p1.y;  p1.y = t;
        t = p2.x; p2.x = -p2.y; p2.y = -t;
        t = u0.x; u0.x = u0.y;  u0.y = t;
        t = u1.x; u1.x = u1.y;  u1.y = t;
        t = u2.x; u2.x = -u2.y; u2.y = -t;
        t = f0.x; f0.x = -f0.y; f0.y = -t;
        t = f1.x; f1.x = -f1.y; f1.y = -t;
        t = f2.x; f2.x = f2.y;  f2.y = t;
    }

    float d0 = fabsf(p0.y - p0.x), d1 = fabsf(p1.y - p1.x), d2 = fabsf(p2.y - p2.x);
    bool cont = fmaxf(d0, fmaxf(d1, d2)) < 0.005f;

    const float G = 5.0f / 3.0f;
    float c0 = sqrtf(G * p1.x / p0.x);
    float c1 = sqrtf(G * p1.y / p0.y);
    float dv = p2.y - p2.x;
    float num = (c0 + c1) - (1.0f / 3.0f) * dv;
    float den = c0 * __powf(p1.x, -0.2f) + c1 * __powf(p1.y, -0.2f);
    float ps = fmaxf(num / den, 1e-8f);
    float ps2 = ps * ps;
    float p_star = ps2 * ps2 * ps;
    bool vac = dv >= 3.0f * (c0 + c1);
    bool dsb = p_star > fmaxf(p1.x, p1.y);
    bool drb = p_star < fminf(p1.x, p1.y);
    int label = vac ? 3 : (drb ? 1 : (dsb ? 0 : 2));

    bool want = valid && !cont && (label < 3);

    if (valid && !want) {
        if (cont) {
            float inv = 1.0f / (cm - cn);
            float cmcn = cm * cn;
            float h0 = (cm * f0.x - cn * f0.y + cmcn * (u0.y - u0.x)) * inv;
            float h1 = (cm * f1.x - cn * f1.y + cmcn * (u1.y - u1.x)) * inv;
            float h2 = (cm * f2.x - cn * f2.y + cmcn * (u2.y - u2.x)) * inv;
            if (flip) { h0 = -h0; h1 = -h1; }
            out[(size_t)n * 3 + 0] = h0;
            out[(size_t)n * 3 + 1] = h1;
            out[(size_t)n * 3 + 2] = h2;
        } else {
            out[(size_t)n * 3 + 0] = 0.0f;
            out[(size_t)n * 3 + 1] = 0.0f;
            out[(size_t)n * 3 + 2] = 0.0f;
        }
    }

    int w = threadIdx.x >> 5;
    unsigned lane = threadIdx.x & 31;
    unsigned lt_mask = (1u << lane) - 1u;
    unsigned m[3];
    #pragma unroll
    for (int l = 0; l < 3; l++) {
        m[l] = __ballot_sync(0xffffffffu, want && label == l);
        if (lane == 0) s_cnt[l][w] = __popc(m[l]);
    }
    __syncthreads();
    if (threadIdx.x < 3) {
        int l = threadIdx.x;
        int tot = 0;
        #pragma unroll
        for (int i = 0; i < TA / 32; i++) tot += s_cnt[l][i];
        int base = tot ? atomicAdd(&g_cnt[l], tot) : 0;
        #pragma unroll
        for (int i = 0; i < TA / 32; i++) {
            s_base[l][i] = base;
            base += s_cnt[l][i];
        }
    }
    __syncthreads();

    if (want) {
        int pos = s_base[label][w] + __popc(m[label] & lt_mask);
        float4* dst = reinterpret_cast<float4*>(g_feat[label][pos]);
        dst[0] = make_float4(p0.x, p0.y, p1.x, p1.y);
        dst[1] = make_float4(p2.x, p2.y, u0.x, u0.y);
        dst[2] = make_float4(u1.x, u1.y, u2.x, u2.y);
        dst[3] = make_float4(f0.x, f0.y, f1.x, f1.y);
        dst[4] = make_float4(f2.x, f2.y, cm, cn);
        g_tag[label][pos] = n | (flip ? (int)0x80000000 : 0);
    }
}

// ---------------- Phase B ----------------
#define TB   256
#define CPT  4
#define GB   (TB * CPT)    // 1024 cells/tile
#define SFT  22            // float2-aligned, conflict-free stride
#define NCH  4             // 4 chunks of 16 hidden units
#define GRID_B 296

#define OFF_FT  0
#define OFF_W1  (GB * SFT)                 // 22528
#define OFF_B1  (OFF_W1 + 3 * 1280)
#define OFF_W2  (OFF_B1 + 3 * 64)
#define OFF_B2  (OFF_W2 + 3 * 192)
#define SMEM_FLOATS (OFF_B2 + 12)
#define SMEM_B_BYTES (SMEM_FLOATS * 4)

__global__ void __launch_bounds__(TB, 2)
phaseB(const float* __restrict__ W1_ds, const float* __restrict__ b1_ds,
       const float* __restrict__ W2_ds, const float* __restrict__ b2_ds,
       const float* __restrict__ W1_dr, const float* __restrict__ b1_dr,
       const float* __restrict__ W2_dr, const float* __restrict__ b2_dr,
       const float* __restrict__ W1_rs, const float* __restrict__ b1_rs,
       const float* __restrict__ W2_rs, const float* __restrict__ b2_rs,
       float* __restrict__ out)
{
    extern __shared__ float sm[];
    float* sft = sm + OFF_FT;
    float* w1s = sm + OFF_W1;
    float* b1s = sm + OFF_B1;
    float* w2s = sm + OFF_W2;
    float* b2s = sm + OFF_B2;

    {
        const float* w1p[3] = {W1_ds, W1_dr, W1_rs};
        const float* b1p[3] = {b1_ds, b1_dr, b1_rs};
        const float* w2p[3] = {W2_ds, W2_dr, W2_rs};
        const float* b2p[3] = {b2_ds, b2_dr, b2_rs};
        #pragma unroll
        for (int mI = 0; mI < 3; mI++) {
            for (int i = threadIdx.x; i < 1280; i += TB) w1s[mI * 1280 + i] = w1p[mI][i];
            for (int i = threadIdx.x; i < 64; i += TB)   b1s[mI * 64 + i] = b1p[mI][i];
            for (int i = threadIdx.x; i < 192; i += TB) {
                int h = i / 3, j = i % 3;
                w2s[mI * 192 + j * 64 + h] = w2p[mI][i];
            }
            if (threadIdx.x < 3) b2s[mI * 4 + threadIdx.x] = b2p[mI][threadIdx.x];
        }
    }

    int c0 = g_cnt[0], c1 = g_cnt[1], c2 = g_cnt[2];
    int t0 = (c0 + GB - 1) / GB, t1 = (c1 + GB - 1) / GB, t2 = (c2 + GB - 1) / GB;
    int T = t0 + t1 + t2;

    int lane = threadIdx.x & 31;
    int w = threadIdx.x >> 5;
    int slot0 = w * (32 * CPT) + lane;   // cell c of this lane -> slot0 + 32*c

    for (int t = blockIdx.x; t < T; t += GRID_B) {
        int l, ti, cnt;
        if (t < t0)           { l = 0; ti = t;           cnt = c0; }
        else if (t < t0 + t1) { l = 1; ti = t - t0;      cnt = c1; }
        else                  { l = 2; ti = t - t0 - t1; cnt = c2; }
        int base = ti * GB;
        int todo = min(GB, cnt - base);

        __syncthreads();
        // stage features (float2 granularity: 10 pairs / record)
        {
            const float2* src = reinterpret_cast<const float2*>(g_feat[l][base]);
            for (int i = threadIdx.x; i < GB * 10; i += TB) {
                int slot = i / 10, q = i - slot * 10;
                float2 v = make_float2(0.f, 0.f);
                if (slot < todo) v = src[(size_t)slot * 10 + q];
                *reinterpret_cast<float2*>(&sft[slot * SFT + 2 * q]) = v;
            }
        }
        __syncthreads();

        const float* w1 = w1s + l * 1280;
        const float* w2 = w2s + l * 192;
        const unsigned long long* b1v =
            reinterpret_cast<const unsigned long long*>(b1s + l * 64);

        float oj[CPT][3];
        #pragma unroll
        for (int c = 0; c < CPT; c++) { oj[c][0] = 0.f; oj[c][1] = 0.f; oj[c][2] = 0.f; }

        const float* fcol = sft + slot0 * SFT;

        #pragma unroll
        for (int chunk = 0; chunk < NCH; chunk++) {
            // 16 hidden units = 8 f32x2 accumulators per cell
            unsigned long long bb[8];
            #pragma unroll
            for (int i = 0; i < 8; i++) bb[i] = b1v[chunk * 8 + i];
            unsigned long long ha[CPT][8];
            #pragma unroll
            for (int c = 0; c < CPT; c++)
                #pragma unroll
                for (int i = 0; i < 8; i++) ha[c][i] = bb[i];

            #pragma unroll 5
            for (int kp = 0; kp < 10; kp++) {
                float2 xv[CPT];
                #pragma unroll
                for (int c = 0; c < CPT; c++)
                    xv[c] = *reinterpret_cast<const float2*>(
                                &fcol[c * (32 * SFT) + 2 * kp]);
                #pragma unroll
                for (int h = 0; h < 2; h++) {
                    int k = 2 * kp + h;
                    const ulonglong2* wrow =
                        reinterpret_cast<const ulonglong2*>(w1 + k * 64 + chunk * 16);
                    ulonglong2 wq0 = wrow[0], wq1 = wrow[1];
                    ulonglong2 wq2 = wrow[2], wq3 = wrow[3];
                    #pragma unroll
                    for (int c = 0; c < CPT; c++) {
                        float x = h ? xv[c].y : xv[c].x;
                        unsigned long long x2 = pack2(x, x);
                        ha[c][0] = fma2(x2, wq0.x, ha[c][0]);
                        ha[c][1] = fma2(x2, wq0.y, ha[c][1]);
                        ha[c][2] = fma2(x2, wq1.x, ha[c][2]);
                        ha[c][3] = fma2(x2, wq1.y, ha[c][3]);
                        ha[c][4] = fma2(x2, wq2.x, ha[c][4]);
                        ha[c][5] = fma2(x2, wq2.y, ha[c][5]);
                        ha[c][6] = fma2(x2, wq3.x, ha[c][6]);
                        ha[c][7] = fma2(x2, wq3.y, ha[c][7]);
                    }
                }
            }

            // tanh
            #pragma unroll
            for (int c = 0; c < CPT; c++)
                #pragma unroll
                for (int i = 0; i < 8; i++) {
                    float a, b;
                    unpack2(ha[c][i], a, b);
                    ha[c][i] = pack2(tanh_fast(a), tanh_fast(b));
                }

            // layer 2 partial dots
            #pragma unroll
            for (int j = 0; j < 3; j++) {
                const ulonglong2* w2row =
                    reinterpret_cast<const ulonglong2*>(w2 + j * 64 + chunk * 16);
                ulonglong2 va = w2row[0], vb = w2row[1];
                ulonglong2 vc = w2row[2], vd = w2row[3];
                #pragma unroll
                for (int c = 0; c < CPT; c++) {
                    unsigned long long t0a = fma2(ha[c][0], va.x,
                                            fma2(ha[c][1], va.y, pack2(0.f, 0.f)));
                    unsigned long long t1a = fma2(ha[c][2], vb.x,
                                            fma2(ha[c][3], vb.y, pack2(0.f, 0.f)));
                    unsigned long long t2a = fma2(ha[c][4], vc.x,
                                            fma2(ha[c][5], vc.y, t0a));
                    unsigned long long t3a = fma2(ha[c][6], vd.x,
                                            fma2(ha[c][7], vd.y, t1a));
                    float a, b, d, e;
                    unpack2(t2a, a, b);
                    unpack2(t3a, d, e);
                    oj[c][j] += (a + b) + (d + e);
                }
            }
        }

        #pragma unroll
        for (int c = 0; c < CPT; c++) {
            int gslot = base + slot0 + 32 * c;
            if (gslot < cnt) {
                int tag = g_tag[l][gslot];
                int cell = tag & 0x7FFFFFFF;
                bool fl = tag < 0;
                float o0 = oj[c][0] + b2s[l * 4 + 0];
                float o1 = oj[c][1] + b2s[l * 4 + 1];
                float o2 = oj[c][2] + b2s[l * 4 + 2];
                if (fl) { o0 = -o0; o1 = -o1; }
                out[(size_t)cell * 3 + 0] = o0;
                out[(size_t)cell * 3 + 1] = o1;
                out[(size_t)cell * 3 + 2] = o2;
            }
        }
    }
}

// ---------------- launch ----------------
extern "C" void kernel_launch(void* const* d_in, const int* in_sizes, int n_in,
                              void* d_out, int out_size) {
    const float* P     = (const float*)d_in[0];
    const float* U     = (const float*)d_in[1];
    const float* F     = (const float*)d_in[2];
    const float* cmax  = (const float*)d_in[3];
    const float* cmin  = (const float*)d_in[4];
    const float* W1_ds = (const float*)d_in[5];
    const float* b1_ds = (const float*)d_in[6];
    const float* W2_ds = (const float*)d_in[7];
    const float* b2_ds = (const float*)d_in[8];
    const float* W1_dr = (const float*)d_in[9];
    const float* b1_dr = (const float*)d_in[10];
    const float* W2_dr = (const float*)d_in[11];
    const float* b2_dr = (const float*)d_in[12];
    const float* W1_rs = (const float*)d_in[13];
    const float* b1_rs = (const float*)d_in[14];
    const float* W2_rs = (const float*)d_in[15];
    const float* b2_rs = (const float*)d_in[16];

    int N = in_sizes[3];
    float* out = (float*)d_out;

    cudaFuncSetAttribute(phaseB, cudaFuncAttributeMaxDynamicSharedMemorySize,
                         SMEM_B_BYTES);

    void* cnt_ptr = nullptr;
    cudaGetSymbolAddress(&cnt_ptr, g_cnt);
    cudaMemsetAsync(cnt_ptr, 0, 3 * sizeof(int));

    phaseA<<<(N + TA - 1) / TA, TA>>>(P, U, F, cmax, cmin, out, N);
    phaseB<<<GRID_B, TB, SMEM_B_BYTES>>>(W1_ds, b1_ds, W2_ds, b2_ds,
                                         W1_dr, b1_dr, W2_dr, b2_dr,
                                         W1_rs, b1_rs, W2_rs, b2_rs,
                                         out);
}

// round 6
// speedup vs baseline: 1.7044x; 1.1116x over previous
#include <cuda_runtime.h>
#include <math.h>

#define NMAX (1 << 20)

// ---------------- global scratch ----------------
__device__ float g_feat[3][NMAX][20];
__device__ int   g_tag[3][NMAX];
__device__ int   g_cnt[4];   // [0..2] = label counts, [3] = tile ticket

// ---------------- helpers ----------------
__device__ __forceinline__ unsigned long long fma2(unsigned long long a,
                                                   unsigned long long b,
                                                   unsigned long long c) {
    unsigned long long d;
    asm("fma.rn.f32x2 %0, %1, %2, %3;" : "=l"(d) : "l"(a), "l"(b), "l"(c));
    return d;
}
__device__ __forceinline__ unsigned long long pack2(float a, float b) {
    unsigned long long r;
    asm("mov.b64 %0, {%1, %2};" : "=l"(r) : "f"(a), "f"(b));
    return r;
}
__device__ __forceinline__ void unpack2(unsigned long long v, float& a, float& b) {
    asm("mov.b64 {%0, %1}, %2;" : "=f"(a), "=f"(b) : "l"(v));
}
__device__ __forceinline__ float tanh_approx(float x) {
    float r;
    asm("tanh.approx.f32 %0, %1;" : "=f"(r) : "f"(x));
    return r;
}

// ---------------- Phase A ----------------
#define TA 256
__global__ void __launch_bounds__(TA)
phaseA(const float* __restrict__ P, const float* __restrict__ U,
       const float* __restrict__ F,
       const float* __restrict__ cmax, const float* __restrict__ cmin,
       float* __restrict__ out, int N)
{
    __shared__ int s_cnt[3][TA / 32];
    __shared__ int s_base[3][TA / 32];

    int n = blockIdx.x * TA + threadIdx.x;
    bool valid = n < N;
    int ncl = valid ? n : 0;

    const float2* P2 = reinterpret_cast<const float2*>(P + (size_t)ncl * 6);
    const float2* U2 = reinterpret_cast<const float2*>(U + (size_t)ncl * 6);
    const float2* F2 = reinterpret_cast<const float2*>(F + (size_t)ncl * 6);
    float2 p0 = P2[0], p1 = P2[1], p2 = P2[2];
    float2 u0 = U2[0], u1 = U2[1], u2 = U2[2];
    float2 f0 = F2[0], f1 = F2[1], f2 = F2[2];
    float cm = cmax[ncl], cn = cmin[ncl];

    bool flip = p1.y > p1.x;
    if (flip) {
        float t;
        t = p0.x; p0.x = p0.y;  p0.y = t;
        t = p1.x; p1.x = p1.y;  p1.y = t;
        t = p2.x; p2.x = -p2.y; p2.y = -t;
        t = u0.x; u0.x = u0.y;  u0.y = t;
        t = u1.x; u1.x = u1.y;  u1.y = t;
        t = u2.x; u2.x = -u2.y; u2.y = -t;
        t = f0.x; f0.x = -f0.y; f0.y = -t;
        t = f1.x; f1.x = -f1.y; f1.y = -t;
        t = f2.x; f2.x = f2.y;  f2.y = t;
    }

    float d0 = fabsf(p0.y - p0.x), d1 = fabsf(p1.y - p1.x), d2 = fabsf(p2.y - p2.x);
    bool cont = fmaxf(d0, fmaxf(d1, d2)) < 0.005f;

    const float G = 5.0f / 3.0f;
    float c0 = sqrtf(G * p1.x / p0.x);
    float c1 = sqrtf(G * p1.y / p0.y);
    float dv = p2.y - p2.x;
    float num = (c0 + c1) - (1.0f / 3.0f) * dv;
    float den = c0 * __powf(p1.x, -0.2f) + c1 * __powf(p1.y, -0.2f);
    float ps = fmaxf(num / den, 1e-8f);
    float ps2 = ps * ps;
    float p_star = ps2 * ps2 * ps;
    bool vac = dv >= 3.0f * (c0 + c1);
    bool dsb = p_star > fmaxf(p1.x, p1.y);
    bool drb = p_star < fminf(p1.x, p1.y);
    int label = vac ? 3 : (drb ? 1 : (dsb ? 0 : 2));

    bool want = valid && !cont && (label < 3);

    if (valid && !want) {
        if (cont) {
            float inv = 1.0f / (cm - cn);
            float cmcn = cm * cn;
            float h0 = (cm * f0.x - cn * f0.y + cmcn * (u0.y - u0.x)) * inv;
            float h1 = (cm * f1.x - cn * f1.y + cmcn * (u1.y - u1.x)) * inv;
            float h2 = (cm * f2.x - cn * f2.y + cmcn * (u2.y - u2.x)) * inv;
            if (flip) { h0 = -h0; h1 = -h1; }
            out[(size_t)n * 3 + 0] = h0;
            out[(size_t)n * 3 + 1] = h1;
            out[(size_t)n * 3 + 2] = h2;
        } else {
            out[(size_t)n * 3 + 0] = 0.0f;
            out[(size_t)n * 3 + 1] = 0.0f;
            out[(size_t)n * 3 + 2] = 0.0f;
        }
    }

    int w = threadIdx.x >> 5;
    unsigned lane = threadIdx.x & 31;
    unsigned lt_mask = (1u << lane) - 1u;
    unsigned m[3];
    #pragma unroll
    for (int l = 0; l < 3; l++) {
        m[l] = __ballot_sync(0xffffffffu, want && label == l);
        if (lane == 0) s_cnt[l][w] = __popc(m[l]);
    }
    __syncthreads();
    if (threadIdx.x < 3) {
        int l = threadIdx.x;
        int tot = 0;
        #pragma unroll
        for (int i = 0; i < TA / 32; i++) tot += s_cnt[l][i];
        int base = tot ? atomicAdd(&g_cnt[l], tot) : 0;
        #pragma unroll
        for (int i = 0; i < TA / 32; i++) {
            s_base[l][i] = base;
            base += s_cnt[l][i];
        }
    }
    __syncthreads();

    if (want) {
        int pos = s_base[label][w] + __popc(m[label] & lt_mask);
        float4* dst = reinterpret_cast<float4*>(g_feat[label][pos]);
        dst[0] = make_float4(p0.x, p0.y, p1.x, p1.y);
        dst[1] = make_float4(p2.x, p2.y, u0.x, u0.y);
        dst[2] = make_float4(u1.x, u1.y, u2.x, u2.y);
        dst[3] = make_float4(f0.x, f0.y, f1.x, f1.y);
        dst[4] = make_float4(f2.x, f2.y, cm, cn);
        g_tag[label][pos] = n | (flip ? (int)0x80000000 : 0);
    }
}

// ---------------- Phase B ----------------
#define TB   256
#define CPT  4
#define GB   (TB * CPT)    // 1024 cells/tile
#define SFT  22
#define NCH  4
#define GRID_B 296

#define OFF_FT  0
#define OFF_W1  (GB * SFT)
#define OFF_B1  (OFF_W1 + 3 * 1280)
#define OFF_W2  (OFF_B1 + 3 * 64)
#define OFF_B2  (OFF_W2 + 3 * 192)
#define SMEM_FLOATS (OFF_B2 + 12)
#define SMEM_B_BYTES (SMEM_FLOATS * 4)

__global__ void __launch_bounds__(TB, 2)
phaseB(const float* __restrict__ W1_ds, const float* __restrict__ b1_ds,
       const float* __restrict__ W2_ds, const float* __restrict__ b2_ds,
       const float* __restrict__ W1_dr, const float* __restrict__ b1_dr,
       const float* __restrict__ W2_dr, const float* __restrict__ b2_dr,
       const float* __restrict__ W1_rs, const float* __restrict__ b1_rs,
       const float* __restrict__ W2_rs, const float* __restrict__ b2_rs,
       float* __restrict__ out)
{
    extern __shared__ float sm[];
    float* sft = sm + OFF_FT;
    float* w1s = sm + OFF_W1;
    float* b1s = sm + OFF_B1;
    float* w2s = sm + OFF_W2;
    float* b2s = sm + OFF_B2;
    __shared__ int s_t;

    {
        const float* w1p[3] = {W1_ds, W1_dr, W1_rs};
        const float* b1p[3] = {b1_ds, b1_dr, b1_rs};
        const float* w2p[3] = {W2_ds, W2_dr, W2_rs};
        const float* b2p[3] = {b2_ds, b2_dr, b2_rs};
        #pragma unroll
        for (int mI = 0; mI < 3; mI++) {
            for (int i = threadIdx.x; i < 1280; i += TB) w1s[mI * 1280 + i] = w1p[mI][i];
            for (int i = threadIdx.x; i < 64; i += TB)   b1s[mI * 64 + i] = b1p[mI][i];
            for (int i = threadIdx.x; i < 192; i += TB) {
                int h = i / 3, j = i % 3;
                w2s[mI * 192 + j * 64 + h] = w2p[mI][i];
            }
            if (threadIdx.x < 3) b2s[mI * 4 + threadIdx.x] = b2p[mI][threadIdx.x];
        }
    }

    int c0 = g_cnt[0], c1 = g_cnt[1], c2 = g_cnt[2];
    int t0 = (c0 + GB - 1) / GB, t1 = (c1 + GB - 1) / GB, t2 = (c2 + GB - 1) / GB;
    int T = t0 + t1 + t2;

    int lane = threadIdx.x & 31;
    int w = threadIdx.x >> 5;
    int slot0 = w * (32 * CPT) + lane;

    for (;;) {
        if (threadIdx.x == 0) s_t = atomicAdd(&g_cnt[3], 1);
        // barrier: publishes s_t AND guarantees all warps finished reading
        // the previous tile's staged features before we overwrite them
        __syncthreads();
        int t = s_t;
        if (t >= T) break;

        int l, ti, cnt;
        if (t < t0)           { l = 0; ti = t;           cnt = c0; }
        else if (t < t0 + t1) { l = 1; ti = t - t0;      cnt = c1; }
        else                  { l = 2; ti = t - t0 - t1; cnt = c2; }
        int base = ti * GB;
        int todo = min(GB, cnt - base);

        {
            const float2* src = reinterpret_cast<const float2*>(g_feat[l][base]);
            for (int i = threadIdx.x; i < GB * 10; i += TB) {
                int slot = i / 10, q = i - slot * 10;
                float2 v = make_float2(0.f, 0.f);
                if (slot < todo) v = src[(size_t)slot * 10 + q];
                *reinterpret_cast<float2*>(&sft[slot * SFT + 2 * q]) = v;
            }
        }
        __syncthreads();

        const float* w1 = w1s + l * 1280;
        const float* w2 = w2s + l * 192;
        const unsigned long long* b1v =
            reinterpret_cast<const unsigned long long*>(b1s + l * 64);

        float oj[CPT][3];
        #pragma unroll
        for (int c = 0; c < CPT; c++) { oj[c][0] = 0.f; oj[c][1] = 0.f; oj[c][2] = 0.f; }

        const float* fcol = sft + slot0 * SFT;

        #pragma unroll
        for (int chunk = 0; chunk < NCH; chunk++) {
            unsigned long long bb[8];
            #pragma unroll
            for (int i = 0; i < 8; i++) bb[i] = b1v[chunk * 8 + i];
            unsigned long long ha[CPT][8];
            #pragma unroll
            for (int c = 0; c < CPT; c++)
                #pragma unroll
                for (int i = 0; i < 8; i++) ha[c][i] = bb[i];

            #pragma unroll 5
            for (int kp = 0; kp < 10; kp++) {
                float2 xv[CPT];
                #pragma unroll
                for (int c = 0; c < CPT; c++)
                    xv[c] = *reinterpret_cast<const float2*>(
                                &fcol[c * (32 * SFT) + 2 * kp]);
                #pragma unroll
                for (int h = 0; h < 2; h++) {
                    int k = 2 * kp + h;
                    const ulonglong2* wrow =
                        reinterpret_cast<const ulonglong2*>(w1 + k * 64 + chunk * 16);
                    ulonglong2 wq0 = wrow[0], wq1 = wrow[1];
                    ulonglong2 wq2 = wrow[2], wq3 = wrow[3];
                    #pragma unroll
                    for (int c = 0; c < CPT; c++) {
                        float x = h ? xv[c].y : xv[c].x;
                        unsigned long long x2 = pack2(x, x);
                        ha[c][0] = fma2(x2, wq0.x, ha[c][0]);
                        ha[c][1] = fma2(x2, wq0.y, ha[c][1]);
                        ha[c][2] = fma2(x2, wq1.x, ha[c][2]);
                        ha[c][3] = fma2(x2, wq1.y, ha[c][3]);
                        ha[c][4] = fma2(x2, wq2.x, ha[c][4]);
                        ha[c][5] = fma2(x2, wq2.y, ha[c][5]);
                        ha[c][6] = fma2(x2, wq3.x, ha[c][6]);
                        ha[c][7] = fma2(x2, wq3.y, ha[c][7]);
                    }
                }
            }

            // tanh (single-MUFU approx)
            #pragma unroll
            for (int c = 0; c < CPT; c++)
                #pragma unroll
                for (int i = 0; i < 8; i++) {
                    float a, b;
                    unpack2(ha[c][i], a, b);
                    ha[c][i] = pack2(tanh_approx(a), tanh_approx(b));
                }

            #pragma unroll
            for (int j = 0; j < 3; j++) {
                const ulonglong2* w2row =
                    reinterpret_cast<const ulonglong2*>(w2 + j * 64 + chunk * 16);
                ulonglong2 va = w2row[0], vb = w2row[1];
                ulonglong2 vc = w2row[2], vd = w2row[3];
                #pragma unroll
                for (int c = 0; c < CPT; c++) {
                    unsigned long long t0a = fma2(ha[c][0], va.x,
                                            fma2(ha[c][1], va.y, pack2(0.f, 0.f)));
                    unsigned long long t1a = fma2(ha[c][2], vb.x,
                                            fma2(ha[c][3], vb.y, pack2(0.f, 0.f)));
                    unsigned long long t2a = fma2(ha[c][4], vc.x,
                                            fma2(ha[c][5], vc.y, t0a));
                    unsigned long long t3a = fma2(ha[c][6], vd.x,
                                            fma2(ha[c][7], vd.y, t1a));
                    float a, b, d, e;
                    unpack2(t2a, a, b);
                    unpack2(t3a, d, e);
                    oj[c][j] += (a + b) + (d + e);
                }
            }
        }

        #pragma unroll
        for (int c = 0; c < CPT; c++) {
            int gslot = base + slot0 + 32 * c;
            if (gslot < cnt) {
                int tag = g_tag[l][gslot];
                int cell = tag & 0x7FFFFFFF;
                bool fl = tag < 0;
                float o0 = oj[c][0] + b2s[l * 4 + 0];
                float o1 = oj[c][1] + b2s[l * 4 + 1];
                float o2 = oj[c][2] + b2s[l * 4 + 2];
                if (fl) { o0 = -o0; o1 = -o1; }
                out[(size_t)cell * 3 + 0] = o0;
                out[(size_t)cell * 3 + 1] = o1;
                out[(size_t)cell * 3 + 2] = o2;
            }
        }
    }
}

// ---------------- launch ----------------
extern "C" void kernel_launch(void* const* d_in, const int* in_sizes, int n_in,
                              void* d_out, int out_size) {
    const float* P     = (const float*)d_in[0];
    const float* U     = (const float*)d_in[1];
    const float* F     = (const float*)d_in[2];
    const float* cmax  = (const float*)d_in[3];
    const float* cmin  = (const float*)d_in[4];
    const float* W1_ds = (const float*)d_in[5];
    const float* b1_ds = (const float*)d_in[6];
    const float* W2_ds = (const float*)d_in[7];
    const float* b2_ds = (const float*)d_in[8];
    const float* W1_dr = (const float*)d_in[9];
    const float* b1_dr = (const float*)d_in[10];
    const float* W2_dr = (const float*)d_in[11];
    const float* b2_dr = (const float*)d_in[12];
    const float* W1_rs = (const float*)d_in[13];
    const float* b1_rs = (const float*)d_in[14];
    const float* W2_rs = (const float*)d_in[15];
    const float* b2_rs = (const float*)d_in[16];

    int N = in_sizes[3];
    float* out = (float*)d_out;

    cudaFuncSetAttribute(phaseB, cudaFuncAttributeMaxDynamicSharedMemorySize,
                         SMEM_B_BYTES);

    void* cnt_ptr = nullptr;
    cudaGetSymbolAddress(&cnt_ptr, g_cnt);
    cudaMemsetAsync(cnt_ptr, 0, 4 * sizeof(int));

    phaseA<<<(N + TA - 1) / TA, TA>>>(P, U, F, cmax, cmin, out, N);
    phaseB<<<GRID_B, TB, SMEM_B_BYTES>>>(W1_ds, b1_ds, W2_ds, b2_ds,
                                         W1_dr, b1_dr, W2_dr, b2_dr,
                                         W1_rs, b1_rs, W2_rs, b2_rs,
                                         out);
}

// round 8
// speedup vs baseline: 1.8700x; 1.0971x over previous
#include <cuda_runtime.h>
#include <math.h>

#define NMAX (1 << 20)

// ---------------- global scratch ----------------
__device__ float g_feat[3][NMAX][20];
__device__ int   g_tag[3][NMAX];
__device__ int   g_cnt[8];   // [0..2] counts, [3] tile ticket, [4] done-blocks

// ---------------- helpers ----------------
__device__ __forceinline__ unsigned long long fma2(unsigned long long a,
                                                   unsigned long long b,
                                                   unsigned long long c) {
    unsigned long long d;
    asm("fma.rn.f32x2 %0, %1, %2, %3;" : "=l"(d) : "l"(a), "l"(b), "l"(c));
    return d;
}
__device__ __forceinline__ unsigned long long pack2(float a, float b) {
    unsigned long long r;
    asm("mov.b64 %0, {%1, %2};" : "=l"(r) : "f"(a), "f"(b));
    return r;
}
__device__ __forceinline__ void unpack2(unsigned long long v, float& a, float& b) {
    asm("mov.b64 {%0, %1}, %2;" : "=f"(a), "=f"(b) : "l"(v));
}
__device__ __forceinline__ float tanh_approx(float x) {
    float r;
    asm("tanh.approx.f32 %0, %1;" : "=f"(r) : "f"(x));
    return r;
}
__device__ __forceinline__ unsigned smem_u32(const void* p) {
    unsigned r;
    asm("{ .reg .u64 t; cvta.to.shared.u64 t, %1; cvt.u32.u64 %0, t; }"
        : "=r"(r) : "l"(p));
    return r;
}
// 8-byte cp.async: dst/src need only 8B alignment (SFT=22 floats = 88B stride)
__device__ __forceinline__ void cp_async8(unsigned dst, const void* src,
                                          unsigned src_sz) {
    asm volatile("cp.async.ca.shared.global [%0], [%1], 8, %2;"
                 :: "r"(dst), "l"(src), "r"(src_sz) : "memory");
}

// ---------------- Phase A ----------------
#define TA 256
__global__ void __launch_bounds__(TA)
phaseA(const float* __restrict__ P, const float* __restrict__ U,
       const float* __restrict__ F,
       const float* __restrict__ cmax, const float* __restrict__ cmin,
       float* __restrict__ out, int N)
{
    __shared__ int s_cnt[3][TA / 32];
    __shared__ int s_base[3][TA / 32];

    int n = blockIdx.x * TA + threadIdx.x;
    bool valid = n < N;
    int ncl = valid ? n : 0;

    const float2* P2 = reinterpret_cast<const float2*>(P + (size_t)ncl * 6);
    const float2* U2 = reinterpret_cast<const float2*>(U + (size_t)ncl * 6);
    const float2* F2 = reinterpret_cast<const float2*>(F + (size_t)ncl * 6);
    float2 p0 = P2[0], p1 = P2[1], p2 = P2[2];
    float2 u0 = U2[0], u1 = U2[1], u2 = U2[2];
    float2 f0 = F2[0], f1 = F2[1], f2 = F2[2];
    float cm = cmax[ncl], cn = cmin[ncl];

    bool flip = p1.y > p1.x;
    if (flip) {
        float t;
        t = p0.x; p0.x = p0.y;  p0.y = t;
        t = p1.x; p1.x = p1.y;  p1.y = t;
        t = p2.x; p2.x = -p2.y; p2.y = -t;
        t = u0.x; u0.x = u0.y;  u0.y = t;
        t = u1.x; u1.x = u1.y;  u1.y = t;
        t = u2.x; u2.x = -u2.y; u2.y = -t;
        t = f0.x; f0.x = -f0.y; f0.y = -t;
        t = f1.x; f1.x = -f1.y; f1.y = -t;
        t = f2.x; f2.x = f2.y;  f2.y = t;
    }

    float d0 = fabsf(p0.y - p0.x), d1 = fabsf(p1.y - p1.x), d2 = fabsf(p2.y - p2.x);
    bool cont = fmaxf(d0, fmaxf(d1, d2)) < 0.005f;

    const float G = 5.0f / 3.0f;
    float c0 = sqrtf(G * p1.x / p0.x);
    float c1 = sqrtf(G * p1.y / p0.y);
    float dv = p2.y - p2.x;
    float num = (c0 + c1) - (1.0f / 3.0f) * dv;
    float den = c0 * __powf(p1.x, -0.2f) + c1 * __powf(p1.y, -0.2f);
    float ps = fmaxf(num / den, 1e-8f);
    float ps2 = ps * ps;
    float p_star = ps2 * ps2 * ps;
    bool vac = dv >= 3.0f * (c0 + c1);
    bool dsb = p_star > fmaxf(p1.x, p1.y);
    bool drb = p_star < fminf(p1.x, p1.y);
    int label = vac ? 3 : (drb ? 1 : (dsb ? 0 : 2));

    bool want = valid && !cont && (label < 3);

    if (valid && !want) {
        if (cont) {
            float inv = 1.0f / (cm - cn);
            float cmcn = cm * cn;
            float h0 = (cm * f0.x - cn * f0.y + cmcn * (u0.y - u0.x)) * inv;
            float h1 = (cm * f1.x - cn * f1.y + cmcn * (u1.y - u1.x)) * inv;
            float h2 = (cm * f2.x - cn * f2.y + cmcn * (u2.y - u2.x)) * inv;
            if (flip) { h0 = -h0; h1 = -h1; }
            out[(size_t)n * 3 + 0] = h0;
            out[(size_t)n * 3 + 1] = h1;
            out[(size_t)n * 3 + 2] = h2;
        } else {
            out[(size_t)n * 3 + 0] = 0.0f;
            out[(size_t)n * 3 + 1] = 0.0f;
            out[(size_t)n * 3 + 2] = 0.0f;
        }
    }

    int w = threadIdx.x >> 5;
    unsigned lane = threadIdx.x & 31;
    unsigned lt_mask = (1u << lane) - 1u;
    unsigned m[3];
    #pragma unroll
    for (int l = 0; l < 3; l++) {
        m[l] = __ballot_sync(0xffffffffu, want && label == l);
        if (lane == 0) s_cnt[l][w] = __popc(m[l]);
    }
    __syncthreads();
    if (threadIdx.x < 3) {
        int l = threadIdx.x;
        int tot = 0;
        #pragma unroll
        for (int i = 0; i < TA / 32; i++) tot += s_cnt[l][i];
        int base = tot ? atomicAdd(&g_cnt[l], tot) : 0;
        #pragma unroll
        for (int i = 0; i < TA / 32; i++) {
            s_base[l][i] = base;
            base += s_cnt[l][i];
        }
    }
    __syncthreads();

    if (want) {
        int pos = s_base[label][w] + __popc(m[label] & lt_mask);
        float4* dst = reinterpret_cast<float4*>(g_feat[label][pos]);
        dst[0] = make_float4(p0.x, p0.y, p1.x, p1.y);
        dst[1] = make_float4(p2.x, p2.y, u0.x, u0.y);
        dst[2] = make_float4(u1.x, u1.y, u2.x, u2.y);
        dst[3] = make_float4(f0.x, f0.y, f1.x, f1.y);
        dst[4] = make_float4(f2.x, f2.y, cm, cn);
        g_tag[label][pos] = n | (flip ? (int)0x80000000 : 0);
    }
}

// ---------------- Phase B ----------------
#define TB   256
#define CPT  2
#define GB   (TB * CPT)    // 512 cells/tile
#define SFT  22
#define NCH  4
#define GRID_B 296

#define OFF_FT0 0
#define OFF_FT1 (GB * SFT)                 // 11264
#define OFF_W1  (2 * GB * SFT)             // 22528
#define OFF_B1  (OFF_W1 + 3 * 1280)
#define OFF_W2  (OFF_B1 + 3 * 64)
#define OFF_B2  (OFF_W2 + 3 * 192)
#define SMEM_FLOATS (OFF_B2 + 12)
#define SMEM_B_BYTES (SMEM_FLOATS * 4)

__global__ void __launch_bounds__(TB, 2)
phaseB(const float* __restrict__ W1_ds, const float* __restrict__ b1_ds,
       const float* __restrict__ W2_ds, const float* __restrict__ b2_ds,
       const float* __restrict__ W1_dr, const float* __restrict__ b1_dr,
       const float* __restrict__ W2_dr, const float* __restrict__ b2_dr,
       const float* __restrict__ W1_rs, const float* __restrict__ b1_rs,
       const float* __restrict__ W2_rs, const float* __restrict__ b2_rs,
       float* __restrict__ out)
{
    extern __shared__ float sm[];
    float* w1s = sm + OFF_W1;
    float* b1s = sm + OFF_B1;
    float* w2s = sm + OFF_W2;
    float* b2s = sm + OFF_B2;
    __shared__ int s_t[2];

    {
        const float* w1p[3] = {W1_ds, W1_dr, W1_rs};
        const float* b1p[3] = {b1_ds, b1_dr, b1_rs};
        const float* w2p[3] = {W2_ds, W2_dr, W2_rs};
        const float* b2p[3] = {b2_ds, b2_dr, b2_rs};
        #pragma unroll
        for (int mI = 0; mI < 3; mI++) {
            for (int i = threadIdx.x; i < 1280; i += TB) w1s[mI * 1280 + i] = w1p[mI][i];
            for (int i = threadIdx.x; i < 64; i += TB)   b1s[mI * 64 + i] = b1p[mI][i];
            for (int i = threadIdx.x; i < 192; i += TB) {
                int h = i / 3, j = i % 3;
                w2s[mI * 192 + j * 64 + h] = w2p[mI][i];
            }
            if (threadIdx.x < 3) b2s[mI * 4 + threadIdx.x] = b2p[mI][threadIdx.x];
        }
    }

    int c0 = g_cnt[0], c1 = g_cnt[1], c2 = g_cnt[2];
    int t0 = (c0 + GB - 1) / GB, t1 = (c1 + GB - 1) / GB, t2 = (c2 + GB - 1) / GB;
    int T = t0 + t1 + t2;

    int lane = threadIdx.x & 31;
    int w = threadIdx.x >> 5;
    int slot0 = w * (32 * CPT) + lane;

    unsigned smbase = smem_u32(sm);

    auto decode = [&](int t, int& l, int& base, int& cnt) {
        if (t < t0)           { l = 0; base = t * GB;             cnt = c0; }
        else if (t < t0 + t1) { l = 1; base = (t - t0) * GB;      cnt = c1; }
        else                  { l = 2; base = (t - t0 - t1) * GB; cnt = c2; }
    };

    // async-stage tile t into buffer buf (8-byte granules, all 8B-aligned)
    auto stage = [&](int t, int buf) {
        int l, base, cnt;
        decode(t, l, base, cnt);
        int todo = min(GB, cnt - base);
        const char* srcb = (const char*)(&g_feat[l][base][0]);
        unsigned dstb = smbase + (buf ? OFF_FT1 * 4 : 0);
        #pragma unroll
        for (int it = 0; it < (GB * 10) / TB; it++) {
            int i = threadIdx.x + it * TB;
            int slot = i / 10, q = i - 10 * slot;
            unsigned dst = dstb + (unsigned)(slot * SFT + 2 * q) * 4u;
            const char* src = srcb + (size_t)(slot * 20 + q * 2) * 4;
            cp_async8(dst, src, slot < todo ? 8u : 0u);
        }
        asm volatile("cp.async.commit_group;" ::: "memory");
    };

    // preamble: draw first two tickets, stage first tile
    if (threadIdx.x == 0) s_t[0] = atomicAdd(&g_cnt[3], 1);
    __syncthreads();                       // publishes s_t[0] + weights
    int t_cur = s_t[0];
    if (t_cur < T) stage(t_cur, 0);
    if (threadIdx.x == 0) s_t[1] = atomicAdd(&g_cnt[3], 1);
    int nslot = 1, cur = 0;

    while (t_cur < T) {
        asm volatile("cp.async.wait_group 0;" ::: "memory");
        __syncthreads();                   // cur buffer ready; s_t[nslot] published
        int t_next = s_t[nslot];
        if (t_next < T) {
            stage(t_next, cur ^ 1);
            if (threadIdx.x == 0) s_t[nslot ^ 1] = atomicAdd(&g_cnt[3], 1);
        }

        // ---- compute tile t_cur from buffer cur ----
        int l, base, cnt;
        decode(t_cur, l, base, cnt);

        const float* sft = sm + (cur ? OFF_FT1 : OFF_FT0);
        const float* w1 = w1s + l * 1280;
        const float* w2 = w2s + l * 192;
        const unsigned long long* b1v =
            reinterpret_cast<const unsigned long long*>(b1s + l * 64);
        const float* fcol = sft + slot0 * SFT;

        unsigned long long oj[CPT][3];
        #pragma unroll
        for (int c = 0; c < CPT; c++)
            #pragma unroll
            for (int j = 0; j < 3; j++) oj[c][j] = pack2(0.f, 0.f);

        #pragma unroll
        for (int chunk = 0; chunk < NCH; chunk++) {
            unsigned long long bb[8];
            #pragma unroll
            for (int i = 0; i < 8; i++) bb[i] = b1v[chunk * 8 + i];
            unsigned long long ha[CPT][8];
            #pragma unroll
            for (int c = 0; c < CPT; c++)
                #pragma unroll
                for (int i = 0; i < 8; i++) ha[c][i] = bb[i];

            #pragma unroll 5
            for (int kp = 0; kp < 10; kp++) {
                float2 xv[CPT];
                #pragma unroll
                for (int c = 0; c < CPT; c++)
                    xv[c] = *reinterpret_cast<const float2*>(
                                &fcol[c * (32 * SFT) + 2 * kp]);
                #pragma unroll
                for (int h = 0; h < 2; h++) {
                    int k = 2 * kp + h;
                    const ulonglong2* wrow =
                        reinterpret_cast<const ulonglong2*>(w1 + k * 64 + chunk * 16);
                    ulonglong2 wq0 = wrow[0], wq1 = wrow[1];
                    ulonglong2 wq2 = wrow[2], wq3 = wrow[3];
                    #pragma unroll
                    for (int c = 0; c < CPT; c++) {
                        float x = h ? xv[c].y : xv[c].x;
                        unsigned long long x2 = pack2(x, x);
                        ha[c][0] = fma2(x2, wq0.x, ha[c][0]);
                        ha[c][1] = fma2(x2, wq0.y, ha[c][1]);
                        ha[c][2] = fma2(x2, wq1.x, ha[c][2]);
                        ha[c][3] = fma2(x2, wq1.y, ha[c][3]);
                        ha[c][4] = fma2(x2, wq2.x, ha[c][4]);
                        ha[c][5] = fma2(x2, wq2.y, ha[c][5]);
                        ha[c][6] = fma2(x2, wq3.x, ha[c][6]);
                        ha[c][7] = fma2(x2, wq3.y, ha[c][7]);
                    }
                }
            }

            #pragma unroll
            for (int c = 0; c < CPT; c++)
                #pragma unroll
                for (int i = 0; i < 8; i++) {
                    float a, b;
                    unpack2(ha[c][i], a, b);
                    ha[c][i] = pack2(tanh_approx(a), tanh_approx(b));
                }

            #pragma unroll
            for (int j = 0; j < 3; j++) {
                const ulonglong2* w2row =
                    reinterpret_cast<const ulonglong2*>(w2 + j * 64 + chunk * 16);
                ulonglong2 va = w2row[0], vb = w2row[1];
                ulonglong2 vc = w2row[2], vd = w2row[3];
                #pragma unroll
                for (int c = 0; c < CPT; c++) {
                    unsigned long long acc = oj[c][j];
                    acc = fma2(ha[c][0], va.x, acc);
                    acc = fma2(ha[c][1], va.y, acc);
                    acc = fma2(ha[c][2], vb.x, acc);
                    acc = fma2(ha[c][3], vb.y, acc);
                    acc = fma2(ha[c][4], vc.x, acc);
                    acc = fma2(ha[c][5], vc.y, acc);
                    acc = fma2(ha[c][6], vd.x, acc);
                    acc = fma2(ha[c][7], vd.y, acc);
                    oj[c][j] = acc;
                }
            }
        }

        #pragma unroll
        for (int c = 0; c < CPT; c++) {
            int gslot = base + slot0 + 32 * c;
            if (gslot < cnt) {
                int tag = g_tag[l][gslot];
                int cell = tag & 0x7FFFFFFF;
                bool fl = tag < 0;
                float o[3];
                #pragma unroll
                for (int j = 0; j < 3; j++) {
                    float a, b;
                    unpack2(oj[c][j], a, b);
                    o[j] = (a + b) + b2s[l * 4 + j];
                }
                if (fl) { o[0] = -o[0]; o[1] = -o[1]; }
                out[(size_t)cell * 3 + 0] = o[0];
                out[(size_t)cell * 3 + 1] = o[1];
                out[(size_t)cell * 3 + 2] = o[2];
            }
        }

        t_cur = t_next;
        nslot ^= 1;
        cur ^= 1;
    }

    // last finished block resets counters for the next graph replay
    __syncthreads();
    if (threadIdx.x == 0) {
        __threadfence();
        int old = atomicAdd(&g_cnt[4], 1);
        if (old == (int)gridDim.x - 1) {
            g_cnt[0] = 0; g_cnt[1] = 0; g_cnt[2] = 0;
            g_cnt[3] = 0; g_cnt[4] = 0;
            __threadfence();
        }
    }
}

// ---------------- launch ----------------
extern "C" void kernel_launch(void* const* d_in, const int* in_sizes, int n_in,
                              void* d_out, int out_size) {
    const float* P     = (const float*)d_in[0];
    const float* U     = (const float*)d_in[1];
    const float* F     = (const float*)d_in[2];
    const float* cmax  = (const float*)d_in[3];
    const float* cmin  = (const float*)d_in[4];
    const float* W1_ds = (const float*)d_in[5];
    const float* b1_ds = (const float*)d_in[6];
    const float* W2_ds = (const float*)d_in[7];
    const float* b2_ds = (const float*)d_in[8];
    const float* W1_dr = (const float*)d_in[9];
    const float* b1_dr = (const float*)d_in[10];
    const float* W2_dr = (const float*)d_in[11];
    const float* b2_dr = (const float*)d_in[12];
    const float* W1_rs = (const float*)d_in[13];
    const float* b1_rs = (const float*)d_in[14];
    const float* W2_rs = (const float*)d_in[15];
    const float* b2_rs = (const float*)d_in[16];

    int N = in_sizes[3];
    float* out = (float*)d_out;

    cudaFuncSetAttribute(phaseB, cudaFuncAttributeMaxDynamicSharedMemorySize,
                         SMEM_B_BYTES);

    phaseA<<<(N + TA - 1) / TA, TA>>>(P, U, F, cmax, cmin, out, N);
    phaseB<<<GRID_B, TB, SMEM_B_BYTES>>>(W1_ds, b1_ds, W2_ds, b2_ds,
                                         W1_dr, b1_dr, W2_dr, b2_dr,
                                         W1_rs, b1_rs, W2_rs, b2_rs,
                                         out);
}

// round 9
// speedup vs baseline: 2.0693x; 1.1066x over previous
#include <cuda_runtime.h>
#include <math.h>

#define NMAX (1 << 20)

// ---------------- global scratch ----------------
__device__ float g_feat[3][NMAX][20];
__device__ int   g_tag[3][NMAX];
__device__ int   g_cnt[8];   // [0..2] counts, [3] tile ticket, [4] done-blocks

// ---------------- helpers ----------------
__device__ __forceinline__ unsigned long long fma2(unsigned long long a,
                                                   unsigned long long b,
                                                   unsigned long long c) {
    unsigned long long d;
    asm("fma.rn.f32x2 %0, %1, %2, %3;" : "=l"(d) : "l"(a), "l"(b), "l"(c));
    return d;
}
__device__ __forceinline__ unsigned long long pack2(float a, float b) {
    unsigned long long r;
    asm("mov.b64 %0, {%1, %2};" : "=l"(r) : "f"(a), "f"(b));
    return r;
}
__device__ __forceinline__ void unpack2(unsigned long long v, float& a, float& b) {
    asm("mov.b64 {%0, %1}, %2;" : "=f"(a), "=f"(b) : "l"(v));
}
__device__ __forceinline__ float tanh_approx(float x) {
    float r;
    asm("tanh.approx.f32 %0, %1;" : "=f"(r) : "f"(x));
    return r;
}
__device__ __forceinline__ unsigned smem_u32(const void* p) {
    unsigned r;
    asm("{ .reg .u64 t; cvta.to.shared.u64 t, %1; cvt.u32.u64 %0, t; }"
        : "=r"(r) : "l"(p));
    return r;
}
__device__ __forceinline__ void mbar_init(unsigned addr, unsigned cnt) {
    asm volatile("mbarrier.init.shared.b64 [%0], %1;" :: "r"(addr), "r"(cnt) : "memory");
}
__device__ __forceinline__ void mbar_expect_tx(unsigned addr, unsigned bytes) {
    asm volatile("mbarrier.arrive.expect_tx.shared.b64 _, [%0], %1;"
                 :: "r"(addr), "r"(bytes) : "memory");
}
// bulk linear copy global->shared, completion via mbarrier tx-bytes (SASS: UBLKCP)
__device__ __forceinline__ void bulk_g2s(unsigned dst, const void* src,
                                         unsigned bytes, unsigned mbar) {
    asm volatile("cp.async.bulk.shared::cluster.global.mbarrier::complete_tx::bytes "
                 "[%0], [%1], %2, [%3];"
                 :: "r"(dst), "l"(src), "r"(bytes), "r"(mbar) : "memory");
}
__device__ __forceinline__ void mbar_wait_parity(unsigned addr, unsigned parity) {
    unsigned done;
    asm volatile(
        "{\n\t.reg .pred p;\n\t"
        "mbarrier.try_wait.parity.acquire.cta.shared::cta.b64 p, [%1], %2;\n\t"
        "selp.b32 %0, 1, 0, p;\n\t}"
        : "=r"(done) : "r"(addr), "r"(parity) : "memory");
    if (!done) {
        asm volatile(
            "{\n\t.reg .pred P1;\n\t"
            "WL_%=:\n\t"
            "mbarrier.try_wait.parity.acquire.cta.shared::cta.b64 P1, [%0], %1, 0x989680;\n\t"
            "@P1 bra.uni WD_%=;\n\t"
            "bra.uni WL_%=;\n\t"
            "WD_%=:\n\t}"
            :: "r"(addr), "r"(parity) : "memory");
    }
}

// ---------------- Phase A ----------------
#define TA 256
__global__ void __launch_bounds__(TA)
phaseA(const float* __restrict__ P, const float* __restrict__ U,
       const float* __restrict__ F,
       const float* __restrict__ cmax, const float* __restrict__ cmin,
       float* __restrict__ out, int N)
{
    __shared__ int s_cnt[3][TA / 32];
    __shared__ int s_base[3][TA / 32];

    int n = blockIdx.x * TA + threadIdx.x;
    bool valid = n < N;
    int ncl = valid ? n : 0;

    const float2* P2 = reinterpret_cast<const float2*>(P + (size_t)ncl * 6);
    const float2* U2 = reinterpret_cast<const float2*>(U + (size_t)ncl * 6);
    const float2* F2 = reinterpret_cast<const float2*>(F + (size_t)ncl * 6);
    float2 p0 = P2[0], p1 = P2[1], p2 = P2[2];
    float2 u0 = U2[0], u1 = U2[1], u2 = U2[2];
    float2 f0 = F2[0], f1 = F2[1], f2 = F2[2];
    float cm = cmax[ncl], cn = cmin[ncl];

    bool flip = p1.y > p1.x;
    if (flip) {
        float t;
        t = p0.x; p0.x = p0.y;  p0.y = t;
        t = p1.x; p1.x = p1.y;  p1.y = t;
        t = p2.x; p2.x = -p2.y; p2.y = -t;
        t = u0.x; u0.x = u0.y;  u0.y = t;
        t = u1.x; u1.x = u1.y;  u1.y = t;
        t = u2.x; u2.x = -u2.y; u2.y = -t;
        t = f0.x; f0.x = -f0.y; f0.y = -t;
        t = f1.x; f1.x = -f1.y; f1.y = -t;
        t = f2.x; f2.x = f2.y;  f2.y = t;
    }

    float d0 = fabsf(p0.y - p0.x), d1 = fabsf(p1.y - p1.x), d2 = fabsf(p2.y - p2.x);
    bool cont = fmaxf(d0, fmaxf(d1, d2)) < 0.005f;

    const float G = 5.0f / 3.0f;
    float c0 = sqrtf(G * p1.x / p0.x);
    float c1 = sqrtf(G * p1.y / p0.y);
    float dv = p2.y - p2.x;
    float num = (c0 + c1) - (1.0f / 3.0f) * dv;
    float den = c0 * __powf(p1.x, -0.2f) + c1 * __powf(p1.y, -0.2f);
    float ps = fmaxf(num / den, 1e-8f);
    float ps2 = ps * ps;
    float p_star = ps2 * ps2 * ps;
    bool vac = dv >= 3.0f * (c0 + c1);
    bool dsb = p_star > fmaxf(p1.x, p1.y);
    bool drb = p_star < fminf(p1.x, p1.y);
    int label = vac ? 3 : (drb ? 1 : (dsb ? 0 : 2));

    bool want = valid && !cont && (label < 3);

    if (valid && !want) {
        if (cont) {
            float inv = 1.0f / (cm - cn);
            float cmcn = cm * cn;
            float h0 = (cm * f0.x - cn * f0.y + cmcn * (u0.y - u0.x)) * inv;
            float h1 = (cm * f1.x - cn * f1.y + cmcn * (u1.y - u1.x)) * inv;
            float h2 = (cm * f2.x - cn * f2.y + cmcn * (u2.y - u2.x)) * inv;
            if (flip) { h0 = -h0; h1 = -h1; }
            out[(size_t)n * 3 + 0] = h0;
            out[(size_t)n * 3 + 1] = h1;
            out[(size_t)n * 3 + 2] = h2;
        } else {
            out[(size_t)n * 3 + 0] = 0.0f;
            out[(size_t)n * 3 + 1] = 0.0f;
            out[(size_t)n * 3 + 2] = 0.0f;
        }
    }

    int w = threadIdx.x >> 5;
    unsigned lane = threadIdx.x & 31;
    unsigned lt_mask = (1u << lane) - 1u;
    unsigned m[3];
    #pragma unroll
    for (int l = 0; l < 3; l++) {
        m[l] = __ballot_sync(0xffffffffu, want && label == l);
        if (lane == 0) s_cnt[l][w] = __popc(m[l]);
    }
    __syncthreads();
    if (threadIdx.x < 3) {
        int l = threadIdx.x;
        int tot = 0;
        #pragma unroll
        for (int i = 0; i < TA / 32; i++) tot += s_cnt[l][i];
        int base = tot ? atomicAdd(&g_cnt[l], tot) : 0;
        #pragma unroll
        for (int i = 0; i < TA / 32; i++) {
            s_base[l][i] = base;
            base += s_cnt[l][i];
        }
    }
    __syncthreads();

    if (want) {
        int pos = s_base[label][w] + __popc(m[label] & lt_mask);
        float4* dst = reinterpret_cast<float4*>(g_feat[label][pos]);
        dst[0] = make_float4(p0.x, p0.y, p1.x, p1.y);
        dst[1] = make_float4(p2.x, p2.y, u0.x, u0.y);
        dst[2] = make_float4(u1.x, u1.y, u2.x, u2.y);
        dst[3] = make_float4(f0.x, f0.y, f1.x, f1.y);
        dst[4] = make_float4(f2.x, f2.y, cm, cn);
        g_tag[label][pos] = n | (flip ? (int)0x80000000 : 0);
    }
}

// ---------------- Phase B ----------------
#define TB   256
#define CPT  2
#define GB   (TB * CPT)    // 512 cells/tile
#define NCH  4
#define GRID_B 296

// smem floats; feature stride = 20 (linear, matches bulk copy)
#define OFF_FT0 0
#define OFF_FT1 (GB * 20)                  // 10240
#define OFF_W1  (2 * GB * 20)              // 20480
#define OFF_B1  (OFF_W1 + 3 * 1280)
#define OFF_W2  (OFF_B1 + 3 * 64)
#define OFF_B2  (OFF_W2 + 3 * 192)
#define SMEM_FLOATS (OFF_B2 + 12)
#define SMEM_B_BYTES (SMEM_FLOATS * 4)
#define TILE_BYTES (GB * 20 * 4)           // 40960

__global__ void __launch_bounds__(TB, 2)
phaseB(const float* __restrict__ W1_ds, const float* __restrict__ b1_ds,
       const float* __restrict__ W2_ds, const float* __restrict__ b2_ds,
       const float* __restrict__ W1_dr, const float* __restrict__ b1_dr,
       const float* __restrict__ W2_dr, const float* __restrict__ b2_dr,
       const float* __restrict__ W1_rs, const float* __restrict__ b1_rs,
       const float* __restrict__ W2_rs, const float* __restrict__ b2_rs,
       float* __restrict__ out)
{
    extern __shared__ float sm[];
    float* w1s = sm + OFF_W1;
    float* b1s = sm + OFF_B1;
    float* w2s = sm + OFF_W2;
    float* b2s = sm + OFF_B2;
    __shared__ __align__(8) unsigned long long s_mbar[2];
    __shared__ int s_t[2];

    {
        const float* w1p[3] = {W1_ds, W1_dr, W1_rs};
        const float* b1p[3] = {b1_ds, b1_dr, b1_rs};
        const float* w2p[3] = {W2_ds, W2_dr, W2_rs};
        const float* b2p[3] = {b2_ds, b2_dr, b2_rs};
        #pragma unroll
        for (int mI = 0; mI < 3; mI++) {
            for (int i = threadIdx.x; i < 1280; i += TB) w1s[mI * 1280 + i] = w1p[mI][i];
            for (int i = threadIdx.x; i < 64; i += TB)   b1s[mI * 64 + i] = b1p[mI][i];
            for (int i = threadIdx.x; i < 192; i += TB) {
                int h = i / 3, j = i % 3;
                w2s[mI * 192 + j * 64 + h] = w2p[mI][i];
            }
            if (threadIdx.x < 3) b2s[mI * 4 + threadIdx.x] = b2p[mI][threadIdx.x];
        }
    }

    int c0 = g_cnt[0], c1 = g_cnt[1], c2 = g_cnt[2];
    int t0 = (c0 + GB - 1) / GB, t1 = (c1 + GB - 1) / GB, t2 = (c2 + GB - 1) / GB;
    int T = t0 + t1 + t2;

    int lane = threadIdx.x & 31;
    int w = threadIdx.x >> 5;
    int slot0 = w * (32 * CPT) + lane;

    unsigned smbase = smem_u32(sm);
    unsigned mb0 = smem_u32(&s_mbar[0]);
    unsigned mb1 = smem_u32(&s_mbar[1]);

    auto decode = [&](int t, int& l, int& base, int& cnt) {
        if (t < t0)           { l = 0; base = t * GB;             cnt = c0; }
        else if (t < t0 + t1) { l = 1; base = (t - t0) * GB;      cnt = c1; }
        else                  { l = 2; base = (t - t0 - t1) * GB; cnt = c2; }
    };

    // stage tile t into buffer buf with ONE bulk copy (tid 0 only)
    auto stage = [&](int t, int buf) {
        int l, base, cnt;
        decode(t, l, base, cnt);
        int todo = min(GB, cnt - base);
        unsigned bytes = (unsigned)todo * 80u;       // multiple of 16
        unsigned mb = buf ? mb1 : mb0;
        mbar_expect_tx(mb, bytes);
        bulk_g2s(smbase + (unsigned)buf * TILE_BYTES,
                 &g_feat[l][base][0], bytes, mb);
    };

    if (threadIdx.x == 0) {
        mbar_init(mb0, 1);
        mbar_init(mb1, 1);
        s_t[0] = atomicAdd(&g_cnt[3], 1);
    }
    __syncthreads();          // weights staged, mbarriers init'd, s_t[0] visible
    int t_cur = s_t[0];
    if (threadIdx.x == 0) {
        if (t_cur < T) stage(t_cur, 0);
        s_t[1] = atomicAdd(&g_cnt[3], 1);
    }
    int nslot = 1, cur = 0;
    unsigned ph[2] = {0u, 0u};

    while (t_cur < T) {
        mbar_wait_parity(cur ? mb1 : mb0, ph[cur]);
        ph[cur] ^= 1u;
        __syncthreads();      // all warps done with buf cur^1; s_t[nslot] visible
        int t_next = s_t[nslot];
        if (threadIdx.x == 0) {
            if (t_next < T) stage(t_next, cur ^ 1);
            s_t[nslot ^ 1] = atomicAdd(&g_cnt[3], 1);
        }

        // ---- compute tile t_cur from buffer cur ----
        int l, base, cnt;
        decode(t_cur, l, base, cnt);

        const float* sft = sm + (cur ? OFF_FT1 : OFF_FT0);
        const float* w1 = w1s + l * 1280;
        const float* w2 = w2s + l * 192;
        const unsigned long long* b1v =
            reinterpret_cast<const unsigned long long*>(b1s + l * 64);
        const float* fcol = sft + slot0 * 20;

        unsigned long long oj[CPT][3];
        #pragma unroll
        for (int c = 0; c < CPT; c++)
            #pragma unroll
            for (int j = 0; j < 3; j++) oj[c][j] = pack2(0.f, 0.f);

        #pragma unroll
        for (int chunk = 0; chunk < NCH; chunk++) {
            unsigned long long bb[8];
            #pragma unroll
            for (int i = 0; i < 8; i++) bb[i] = b1v[chunk * 8 + i];
            unsigned long long ha[CPT][8];
            #pragma unroll
            for (int c = 0; c < CPT; c++)
                #pragma unroll
                for (int i = 0; i < 8; i++) ha[c][i] = bb[i];

            #pragma unroll
            for (int kq = 0; kq < 5; kq++) {
                float4 xq[CPT];
                #pragma unroll
                for (int c = 0; c < CPT; c++)
                    xq[c] = *reinterpret_cast<const float4*>(
                                &fcol[c * (32 * 20) + 4 * kq]);
                #pragma unroll
                for (int h = 0; h < 4; h++) {
                    int k = 4 * kq + h;
                    const ulonglong2* wrow =
                        reinterpret_cast<const ulonglong2*>(w1 + k * 64 + chunk * 16);
                    ulonglong2 wq0 = wrow[0], wq1 = wrow[1];
                    ulonglong2 wq2 = wrow[2], wq3 = wrow[3];
                    #pragma unroll
                    for (int c = 0; c < CPT; c++) {
                        float x = (h == 0) ? xq[c].x : (h == 1) ? xq[c].y
                                : (h == 2) ? xq[c].z : xq[c].w;
                        unsigned long long x2 = pack2(x, x);
                        ha[c][0] = fma2(x2, wq0.x, ha[c][0]);
                        ha[c][1] = fma2(x2, wq0.y, ha[c][1]);
                        ha[c][2] = fma2(x2, wq1.x, ha[c][2]);
                        ha[c][3] = fma2(x2, wq1.y, ha[c][3]);
                        ha[c][4] = fma2(x2, wq2.x, ha[c][4]);
                        ha[c][5] = fma2(x2, wq2.y, ha[c][5]);
                        ha[c][6] = fma2(x2, wq3.x, ha[c][6]);
                        ha[c][7] = fma2(x2, wq3.y, ha[c][7]);
                    }
                }
            }

            #pragma unroll
            for (int c = 0; c < CPT; c++)
                #pragma unroll
                for (int i = 0; i < 8; i++) {
                    float a, b;
                    unpack2(ha[c][i], a, b);
                    ha[c][i] = pack2(tanh_approx(a), tanh_approx(b));
                }

            #pragma unroll
            for (int j = 0; j < 3; j++) {
                const ulonglong2* w2row =
                    reinterpret_cast<const ulonglong2*>(w2 + j * 64 + chunk * 16);
                ulonglong2 va = w2row[0], vb = w2row[1];
                ulonglong2 vc = w2row[2], vd = w2row[3];
                #pragma unroll
                for (int c = 0; c < CPT; c++) {
                    unsigned long long acc = oj[c][j];
                    acc = fma2(ha[c][0], va.x, acc);
                    acc = fma2(ha[c][1], va.y, acc);
                    acc = fma2(ha[c][2], vb.x, acc);
                    acc = fma2(ha[c][3], vb.y, acc);
                    acc = fma2(ha[c][4], vc.x, acc);
                    acc = fma2(ha[c][5], vc.y, acc);
                    acc = fma2(ha[c][6], vd.x, acc);
                    acc = fma2(ha[c][7], vd.y, acc);
                    oj[c][j] = acc;
                }
            }
        }

        #pragma unroll
        for (int c = 0; c < CPT; c++) {
            int gslot = base + slot0 + 32 * c;
            if (gslot < cnt) {
                int tag = g_tag[l][gslot];
                int cell = tag & 0x7FFFFFFF;
                bool fl = tag < 0;
                float o[3];
                #pragma unroll
                for (int j = 0; j < 3; j++) {
                    float a, b;
                    unpack2(oj[c][j], a, b);
                    o[j] = (a + b) + b2s[l * 4 + j];
                }
                if (fl) { o[0] = -o[0]; o[1] = -o[1]; }
                out[(size_t)cell * 3 + 0] = o[0];
                out[(size_t)cell * 3 + 1] = o[1];
                out[(size_t)cell * 3 + 2] = o[2];
            }
        }

        t_cur = t_next;
        nslot ^= 1;
        cur ^= 1;
    }

    // last finished block resets counters for the next graph replay
    __syncthreads();
    if (threadIdx.x == 0) {
        __threadfence();
        int old = atomicAdd(&g_cnt[4], 1);
        if (old == (int)gridDim.x - 1) {
            g_cnt[0] = 0; g_cnt[1] = 0; g_cnt[2] = 0;
            g_cnt[3] = 0; g_cnt[4] = 0;
            __threadfence();
        }
    }
}

// ---------------- launch ----------------
extern "C" void kernel_launch(void* const* d_in, const int* in_sizes, int n_in,
                              void* d_out, int out_size) {
    const float* P     = (const float*)d_in[0];
    const float* U     = (const float*)d_in[1];
    const float* F     = (const float*)d_in[2];
    const float* cmax  = (const float*)d_in[3];
    const float* cmin  = (const float*)d_in[4];
    const float* W1_ds = (const float*)d_in[5];
    const float* b1_ds = (const float*)d_in[6];
    const float* W2_ds = (const float*)d_in[7];
    const float* b2_ds = (const float*)d_in[8];
    const float* W1_dr = (const float*)d_in[9];
    const float* b1_dr = (const float*)d_in[10];
    const float* W2_dr = (const float*)d_in[11];
    const float* b2_dr = (const float*)d_in[12];
    const float* W1_rs = (const float*)d_in[13];
    const float* b1_rs = (const float*)d_in[14];
    const float* W2_rs = (const float*)d_in[15];
    const float* b2_rs = (const float*)d_in[16];

    int N = in_sizes[3];
    float* out = (float*)d_out;

    cudaFuncSetAttribute(phaseB, cudaFuncAttributeMaxDynamicSharedMemorySize,
                         SMEM_B_BYTES);

    phaseA<<<(N + TA - 1) / TA, TA>>>(P, U, F, cmax, cmin, out, N);
    phaseB<<<GRID_B, TB, SMEM_B_BYTES>>>(W1_ds, b1_ds, W2_ds, b2_ds,
                                         W1_dr, b1_dr, W2_dr, b2_dr,
                                         W1_rs, b1_rs, W2_rs, b2_rs,
                                         out);
}